// round 8
// baseline (speedup 1.0000x reference)
#include <cuda_runtime.h>

#define B 8
#define T 2048
#define D 1024
#define HS 64
#define VC 32

typedef unsigned long long ull;

// ---- device scratch ----
__device__ float g_qT[B * HS * T];           // [b][c][t]
__device__ float g_kT[B * HS * T];           // [b][c][t]
__device__ float g_v [B * T * HS];           // [b][t][h]
__device__ float g_s [(size_t)B * T * T];    // [b][t][v] qk-scores (x8)

// ---- packed f32x2 helpers ----
__device__ __forceinline__ ull splat2(float a) {
    ull r; asm("mov.b64 %0, {%1, %1};" : "=l"(r) : "f"(a)); return r;
}
__device__ __forceinline__ ull pack2(float x, float y) {
    ull r; asm("mov.b64 %0, {%1, %2};" : "=l"(r) : "f"(x), "f"(y)); return r;
}
__device__ __forceinline__ void ffma2(ull& d, ull a, ull b) {
    asm("fma.rn.f32x2 %0, %1, %2, %0;" : "+l"(d) : "l"(a), "l"(b));
}
__device__ __forceinline__ void fmul2(ull& d, ull a) {
    asm("mul.rn.f32x2 %0, %0, %1;" : "+l"(d) : "l"(a));
}
__device__ __forceinline__ float2 unpack2(ull v) {
    float2 f; asm("mov.b64 {%0, %1}, %2;" : "=f"(f.x), "=f"(f.y) : "l"(v)); return f;
}
__device__ __forceinline__ void cp_async16(void* smem_dst, const void* gmem_src) {
    unsigned sa = (unsigned)__cvta_generic_to_shared(smem_dst);
    asm volatile("cp.async.cg.shared.global [%0], [%1], 16;" :: "r"(sa), "l"(gmem_src) : "memory");
}
__device__ __forceinline__ void cp_commit() {
    asm volatile("cp.async.commit_group;" ::: "memory");
}
template<int N> __device__ __forceinline__ void cp_wait() {
    asm volatile("cp.async.wait_group %0;" :: "n"(N) : "memory");
}

// =====================================================================
// K1: projections (unchanged)
// =====================================================================
__global__ __launch_bounds__(256) void proj_kernel(
    const float* __restrict__ x,
    const float* __restrict__ Wk, const float* __restrict__ bk,
    const float* __restrict__ Wq, const float* __restrict__ bq,
    const float* __restrict__ Wv, const float* __restrict__ bv)
{
    __shared__ float Xs[2][16][68];
    __shared__ float Ws[2][3][16][68];

    const int m0  = blockIdx.x * 64;
    const int tid = threadIdx.x;
    const int tg  = tid >> 4;
    const int hg  = tid & 15;

    const float* W[3] = {Wk, Wq, Wv};
    const int lr = tid >> 2;
    const int lc = (tid & 3) << 2;

    ull acc[3][4][2];
#pragma unroll
    for (int m = 0; m < 3; m++)
#pragma unroll
        for (int i = 0; i < 4; i++) { acc[m][i][0] = 0ull; acc[m][i][1] = 0ull; }

    float4 rx, rw[3];
    rx = *(const float4*)(x + (size_t)(m0 + lr) * D + lc);
#pragma unroll
    for (int m = 0; m < 3; m++)
        rw[m] = *(const float4*)(W[m] + (size_t)lr * D + lc);

    Xs[0][lc + 0][lr] = rx.x; Xs[0][lc + 1][lr] = rx.y;
    Xs[0][lc + 2][lr] = rx.z; Xs[0][lc + 3][lr] = rx.w;
#pragma unroll
    for (int m = 0; m < 3; m++) {
        Ws[0][m][lc + 0][lr] = rw[m].x; Ws[0][m][lc + 1][lr] = rw[m].y;
        Ws[0][m][lc + 2][lr] = rw[m].z; Ws[0][m][lc + 3][lr] = rw[m].w;
    }
    __syncthreads();

    int buf = 0;
    for (int k0 = 0; k0 < D; k0 += 16) {
        const bool last = (k0 + 16 >= D);
        if (!last) {
            rx = *(const float4*)(x + (size_t)(m0 + lr) * D + k0 + 16 + lc);
#pragma unroll
            for (int m = 0; m < 3; m++)
                rw[m] = *(const float4*)(W[m] + (size_t)lr * D + k0 + 16 + lc);
        }
#pragma unroll
        for (int kk = 0; kk < 16; kk++) {
            float4 a = *(const float4*)&Xs[buf][kk][tg * 4];
            ull as[4] = {splat2(a.x), splat2(a.y), splat2(a.z), splat2(a.w)};
#pragma unroll
            for (int m = 0; m < 3; m++) {
                float4 w = *(const float4*)&Ws[buf][m][kk][hg * 4];
                ull w0 = pack2(w.x, w.y), w1 = pack2(w.z, w.w);
#pragma unroll
                for (int i = 0; i < 4; i++) {
                    ffma2(acc[m][i][0], as[i], w0);
                    ffma2(acc[m][i][1], as[i], w1);
                }
            }
        }
        if (!last) {
            int nb = buf ^ 1;
            Xs[nb][lc + 0][lr] = rx.x; Xs[nb][lc + 1][lr] = rx.y;
            Xs[nb][lc + 2][lr] = rx.z; Xs[nb][lc + 3][lr] = rx.w;
#pragma unroll
            for (int m = 0; m < 3; m++) {
                Ws[nb][m][lc + 0][lr] = rw[m].x; Ws[nb][m][lc + 1][lr] = rw[m].y;
                Ws[nb][m][lc + 2][lr] = rw[m].z; Ws[nb][m][lc + 3][lr] = rw[m].w;
            }
            __syncthreads();
            buf = nb;
        }
    }

    const float* bias[3] = {bk, bq, bv};
    const int b = m0 >> 11;
#pragma unroll
    for (int m = 0; m < 3; m++) {
        float4 bm = *(const float4*)(bias[m] + hg * 4);
        float bb[4] = {bm.x, bm.y, bm.z, bm.w};
#pragma unroll
        for (int i = 0; i < 4; i++) {
            int row = m0 + tg * 4 + i;
            int t   = row & (T - 1);
            float2 v0 = unpack2(acc[m][i][0]);
            float2 v1 = unpack2(acc[m][i][1]);
            float vals[4] = {v0.x + bb[0], v0.y + bb[1], v1.x + bb[2], v1.y + bb[3]};
            if (m == 0) {
#pragma unroll
                for (int j = 0; j < 4; j++)
                    g_kT[(size_t)(b * HS + hg * 4 + j) * T + t] = vals[j];
            } else if (m == 1) {
#pragma unroll
                for (int j = 0; j < 4; j++)
                    g_qT[(size_t)(b * HS + hg * 4 + j) * T + t] = vals[j];
            } else {
                *(float4*)(g_v + (size_t)row * HS + hg * 4) =
                    make_float4(vals[0], vals[1], vals[2], vals[3]);
            }
        }
    }
}

// =====================================================================
// K2: S = 8 * q k^T (unchanged)
// =====================================================================
__global__ __launch_bounds__(256, 1) void qk_kernel()
{
    extern __shared__ float4 sm4[];
    float4* Q4 = sm4;
    float4* K4 = sm4 + 64 * 32;

    const int v0  = blockIdx.x * 256;
    const int t0  = blockIdx.y * 128;
    const int b   = blockIdx.z;
    const int tid = threadIdx.x;

    const float4* qT4 = (const float4*)g_qT;
    const float4* kT4 = (const float4*)g_kT;

#pragma unroll
    for (int it = 0; it < 8; it++) {
        int idx = tid + it * 256;
        int c = idx >> 5, x4 = idx & 31;
        int perm = ((x4 & 1) << 4) | (x4 >> 1);
        Q4[c * 32 + perm] = qT4[(size_t)(b * HS + c) * (T / 4) + (t0 >> 2) + x4];
    }
#pragma unroll
    for (int it = 0; it < 16; it++) {
        int idx = tid + it * 256;
        int c = idx >> 6, x4 = idx & 63;
        int perm = ((x4 & 3) << 4) | (x4 >> 2);
        K4[c * 64 + perm] = kT4[(size_t)(b * HS + c) * (T / 4) + (v0 >> 2) + x4];
    }
    __syncthreads();

    const int tg = tid >> 4;
    const int vg = tid & 15;

    ull acc[8][8];
#pragma unroll
    for (int i = 0; i < 8; i++)
#pragma unroll
        for (int p = 0; p < 8; p++) acc[i][p] = 0ull;

#pragma unroll 4
    for (int c = 0; c < 64; c++) {
        float4 qa = Q4[c * 32 + tg];
        float4 qb = Q4[c * 32 + 16 + tg];
        float4 k0 = K4[c * 64 + vg];
        float4 k1 = K4[c * 64 + 16 + vg];
        float4 k2 = K4[c * 64 + 32 + vg];
        float4 k3 = K4[c * 64 + 48 + vg];
        ull as[8] = {splat2(qa.x), splat2(qa.y), splat2(qa.z), splat2(qa.w),
                     splat2(qb.x), splat2(qb.y), splat2(qb.z), splat2(qb.w)};
        ull kp[8] = {pack2(k0.x, k0.y), pack2(k0.z, k0.w),
                     pack2(k1.x, k1.y), pack2(k1.z, k1.w),
                     pack2(k2.x, k2.y), pack2(k2.z, k2.w),
                     pack2(k3.x, k3.y), pack2(k3.z, k3.w)};
#pragma unroll
        for (int i = 0; i < 8; i++)
#pragma unroll
            for (int p = 0; p < 8; p++) ffma2(acc[i][p], as[i], kp[p]);
    }

#pragma unroll
    for (int i = 0; i < 8; i++) {
        int trow = t0 + tg * 8 + i;
        float* srow = g_s + ((size_t)(b * T + trow)) * T + v0 + vg * 16;
#pragma unroll
        for (int p = 0; p < 4; p++) {
            float2 e0 = unpack2(acc[i][2 * p]), e1 = unpack2(acc[i][2 * p + 1]);
            *(float4*)(srow + 4 * p) =
                make_float4(8.f * e0.x, 8.f * e0.y, 8.f * e1.x, 8.f * e1.y);
        }
    }
}

// =====================================================================
// K3: FUSED rel + online-softmax + PV.
// grid = T/16 = 128 blocks (16 t each), 512 threads.
// chunk = 32 v. Score role: tid<256, thread=(t, vg 0..7, bh 0..1) -> 4v x 4b.
// PV role: all 512, thread=(b, t4, h4). rel streamed once via cp.async,
// issued between score and PV phases so the copy drains under PV compute.
// =====================================================================
__global__ __launch_bounds__(512, 1) void fused_kernel(const float* __restrict__ rel,
                                                       float* __restrict__ out)
{
    extern __shared__ __align__(16) unsigned char smraw[];
    float4* rel_s   = (float4*)smraw;                   // [16t][32v][16c4] 131072 B
    float*  q_s     = (float*)(smraw + 131072);         // [16t][65c][8b]    33280 B
    float*  e_s     = (float*)(smraw + 164352);         // [16t][264]        16896 B
    float*  scale_s = (float*)(smraw + 181248);         // [16t][8b]           512 B
    float*  lfin    = (float*)(smraw + 181760);         // [16t][8b]           512 B

    const int t0  = blockIdx.x * 16;
    const int tid = threadIdx.x;

    // stage q_s[t][c][b]
#pragma unroll
    for (int i = 0; i < 16; i++) {
        int idx = tid + i * 512;              // 0..8191
        int t = idx & 15, c = (idx >> 4) & 63, b = idx >> 10;
        q_s[(t * 65 + c) * 8 + b] = g_qT[(size_t)(b * HS + c) * T + t0 + t];
    }

    // roles
    const int s_t  = tid >> 4;          // score: t
    const int s_vg = (tid >> 1) & 7;    // score: v-group
    const int s_bh = tid & 1;           // score: b-half
    const int p_b  = tid >> 6;          // pv: batch
    const int p_t4 = (tid >> 4) & 3;    // pv: t-quad
    const int p_h4 = tid & 15;          // pv: h-quad
    const int l_t  = tid >> 5;          // loader: t (0..15)
    const int l_v  = tid & 31;          // loader: v (0..31)

    float m_run[4], l_run[4];
#pragma unroll
    for (int j = 0; j < 4; j++) { m_run[j] = -3.4e38f; l_run[j] = 0.f; }
    ull o_acc[4][2];
#pragma unroll
    for (int tt = 0; tt < 4; tt++) { o_acc[tt][0] = 0ull; o_acc[tt][1] = 0ull; }

    const int lswz = (l_v & 15) ^ ((l_t & 1) << 2);

    // preload rel chunk 0
    {
        const float* src = rel + ((size_t)(t0 + l_t) * T + l_v) * HS;
#pragma unroll
        for (int c4 = 0; c4 < 16; c4++)
            cp_async16(&rel_s[(l_t * 32 + l_v) * 16 + (c4 ^ lswz)], src + c4 * 4);
        cp_commit();
    }
    cp_wait<0>();
    __syncthreads();

    const int NT = T / VC;   // 64
    for (int n = 0; n < NT; n++) {
        const int v0 = n * VC;

        // ---------------- score phase (tid < 256) ----------------
        if (tid < 256) {
            ull acc[2][4];
#pragma unroll
            for (int p = 0; p < 2; p++)
#pragma unroll
                for (int j = 0; j < 4; j++) {
                    int b = s_bh * 4 + j;
                    size_t base = ((size_t)(b * T + t0 + s_t)) * T + v0;
                    acc[p][j] = pack2(g_s[base + s_vg + 16 * p],
                                      g_s[base + s_vg + 16 * p + 8]);
                }

            const float* qrow = q_s + (s_t * 65) * 8 + s_bh * 4;
            const float4* rbase = rel_s + (s_t * 32) * 16;
            const int swz0 = s_vg ^ ((s_t & 1) << 2);
            const int swz1 = (s_vg + 8) ^ ((s_t & 1) << 2);

#pragma unroll 4
            for (int c4 = 0; c4 < 16; c4++) {
                float4 r0 = rbase[(s_vg + 0)  * 16 + (c4 ^ swz0)];
                float4 r1 = rbase[(s_vg + 8)  * 16 + (c4 ^ swz1)];
                float4 r2 = rbase[(s_vg + 16) * 16 + (c4 ^ swz0)];
                float4 r3 = rbase[(s_vg + 24) * 16 + (c4 ^ swz1)];
                float rr[4][4] = {{r0.x, r1.x, r2.x, r3.x},
                                  {r0.y, r1.y, r2.y, r3.y},
                                  {r0.z, r1.z, r2.z, r3.z},
                                  {r0.w, r1.w, r2.w, r3.w}};
#pragma unroll
                for (int jc = 0; jc < 4; jc++) {
                    int c = c4 * 4 + jc;
                    float4 qv = *(const float4*)&qrow[c * 8];
                    float qq[4] = {qv.x, qv.y, qv.z, qv.w};
                    ull rp0 = pack2(rr[jc][0], rr[jc][1]);
                    ull rp1 = pack2(rr[jc][2], rr[jc][3]);
#pragma unroll
                    for (int j = 0; j < 4; j++) {
                        ull qs = splat2(qq[j]);
                        ffma2(acc[0][j], rp0, qs);
                        ffma2(acc[1][j], rp1, qs);
                    }
                }
            }

            float sv[4][4];
#pragma unroll
            for (int p = 0; p < 2; p++)
#pragma unroll
                for (int j = 0; j < 4; j++) {
                    float2 f = unpack2(acc[p][j]);
                    sv[2 * p][j]     = f.x;    // v = vg + 16p
                    sv[2 * p + 1][j] = f.y;    // v = vg + 16p + 8
                }

            float scl[4];
#pragma unroll
            for (int j = 0; j < 4; j++) {
                float m = fmaxf(fmaxf(sv[0][j], sv[1][j]), fmaxf(sv[2][j], sv[3][j]));
#pragma unroll
                for (int o = 2; o <= 8; o <<= 1)
                    m = fmaxf(m, __shfl_xor_sync(0xffffffffu, m, o));
                float mnew = fmaxf(m_run[j], m);
                scl[j] = __expf(m_run[j] - mnew);
                m_run[j] = mnew;
            }

            float* ebase = e_s + s_t * 264 + (s_bh * 4) * 32 + s_vg;
#pragma unroll
            for (int j = 0; j < 4; j++) {
                float ls = 0.f;
                float ev[4];
#pragma unroll
                for (int p = 0; p < 4; p++) {
                    ev[p] = __expf(sv[p][j] - m_run[j]);
                    ls += ev[p];
                }
                // sv index p: p0->v=vg, p1->vg+8, p2->vg+16, p3->vg+24
                ebase[j * 32 + 0]  = ev[0];
                ebase[j * 32 + 8]  = ev[1];
                ebase[j * 32 + 16] = ev[2];
                ebase[j * 32 + 24] = ev[3];
#pragma unroll
                for (int o = 2; o <= 8; o <<= 1)
                    ls += __shfl_xor_sync(0xffffffffu, ls, o);
                l_run[j] = l_run[j] * scl[j] + ls;
            }

            if (s_vg == 0)
                *(float4*)&scale_s[s_t * 8 + s_bh * 4] =
                    make_float4(scl[0], scl[1], scl[2], scl[3]);
        }
        __syncthreads();   // e_s/scale_s ready; rel_s reads complete

        // ---------------- issue cp.async for chunk n+1 ----------------
        if (n + 1 < NT) {
            const float* src = rel + ((size_t)(t0 + l_t) * T + v0 + VC + l_v) * HS;
#pragma unroll
            for (int c4 = 0; c4 < 16; c4++)
                cp_async16(&rel_s[(l_t * 32 + l_v) * 16 + (c4 ^ lswz)], src + c4 * 4);
            cp_commit();
        }

        // ---------------- PV phase (all 512) ----------------
        {
#pragma unroll
            for (int tt = 0; tt < 4; tt++) {
                ull s2 = splat2(scale_s[(p_t4 * 4 + tt) * 8 + p_b]);
                fmul2(o_acc[tt][0], s2);
                fmul2(o_acc[tt][1], s2);
            }

            const float* vbase = g_v + ((size_t)(p_b * T + v0)) * HS + p_h4 * 4;
            const float* eb = e_s + p_b * 32;
#pragma unroll 2
            for (int u4 = 0; u4 < 8; u4++) {
                float ec[4][4];
#pragma unroll
                for (int tt = 0; tt < 4; tt++) {
                    float4 e4 = *(const float4*)&eb[(p_t4 * 4 + tt) * 264 + u4 * 4];
                    ec[tt][0] = e4.x; ec[tt][1] = e4.y; ec[tt][2] = e4.z; ec[tt][3] = e4.w;
                }
#pragma unroll
                for (int w = 0; w < 4; w++) {
                    int v = u4 * 4 + w;
                    float4 vv = *(const float4*)(vbase + (size_t)v * HS);
                    ull vp0 = pack2(vv.x, vv.y), vp1 = pack2(vv.z, vv.w);
#pragma unroll
                    for (int tt = 0; tt < 4; tt++) {
                        ull a = splat2(ec[tt][w]);
                        ffma2(o_acc[tt][0], a, vp0);
                        ffma2(o_acc[tt][1], a, vp1);
                    }
                }
            }
        }

        cp_wait<0>();
        __syncthreads();   // rel chunk n+1 ready; e_s reusable
    }

    // ---------------- epilogue ----------------
    if (tid < 256 && s_vg == 0)
        *(float4*)&lfin[s_t * 8 + s_bh * 4] =
            make_float4(l_run[0], l_run[1], l_run[2], l_run[3]);
    __syncthreads();

#pragma unroll
    for (int tt = 0; tt < 4; tt++) {
        int t = p_t4 * 4 + tt;
        float rl = 1.f / lfin[t * 8 + p_b];
        float2 f0 = unpack2(o_acc[tt][0]);
        float2 f1 = unpack2(o_acc[tt][1]);
        *(float4*)(out + ((size_t)(p_b * T + t0 + t)) * HS + p_h4 * 4) =
            make_float4(f0.x * rl, f0.y * rl, f1.x * rl, f1.y * rl);
    }
}

// =====================================================================
extern "C" void kernel_launch(void* const* d_in, const int* in_sizes, int n_in,
                              void* d_out, int out_size)
{
    (void)in_sizes; (void)n_in; (void)out_size;
    const float* x   = (const float*)d_in[0];
    const float* Wk  = (const float*)d_in[1];
    const float* bk  = (const float*)d_in[2];
    const float* Wq  = (const float*)d_in[3];
    const float* bq  = (const float*)d_in[4];
    const float* Wv  = (const float*)d_in[5];
    const float* bv  = (const float*)d_in[6];
    const float* rel = (const float*)d_in[7];
    float* out = (float*)d_out;

    proj_kernel<<<(B * T) / 64, 256>>>(x, Wk, bk, Wq, bq, Wv, bv);

    const int qk_smem = (64 * 32 + 64 * 64) * sizeof(float4);   // 96 KB
    cudaFuncSetAttribute(qk_kernel, cudaFuncAttributeMaxDynamicSharedMemorySize, qk_smem);
    qk_kernel<<<dim3(T / 256, T / 128, B), 256, qk_smem>>>();

    const int f_smem = 182272;   // rel_s + q_s + e_s + scale_s + lfin
    cudaFuncSetAttribute(fused_kernel, cudaFuncAttributeMaxDynamicSharedMemorySize, f_smem);
    fused_kernel<<<T / 16, 512, f_smem>>>(rel, out);
}

// round 9
// speedup vs baseline: 1.3614x; 1.3614x over previous
#include <cuda_runtime.h>
#include <cuda_fp16.h>

#define B 8
#define T 2048
#define D 1024
#define HS 64

typedef unsigned long long ull;

// ---- device scratch ----
__device__ float g_qT[B * HS * T];           // [b][c][t]
__device__ float g_kT[B * HS * T];           // [b][c][t]
__device__ float g_v [B * T * HS];           // [b][t][h]
__device__ float g_s [(size_t)B * T * T];    // [b][t][v] scores

// ---- packed f32x2 helpers (sm_103a FFMA2) ----
__device__ __forceinline__ ull splat2(float a) {
    ull r; asm("mov.b64 %0, {%1, %1};" : "=l"(r) : "f"(a)); return r;
}
__device__ __forceinline__ ull pack2(float x, float y) {
    ull r; asm("mov.b64 %0, {%1, %2};" : "=l"(r) : "f"(x), "f"(y)); return r;
}
__device__ __forceinline__ void ffma2(ull& d, ull a, ull b) {
    asm("fma.rn.f32x2 %0, %1, %2, %0;" : "+l"(d) : "l"(a), "l"(b));
}
__device__ __forceinline__ float2 unpack2(ull v) {
    float2 f; asm("mov.b64 {%0, %1}, %2;" : "=f"(f.x), "=f"(f.y) : "l"(v)); return f;
}
__device__ __forceinline__ void cp_async16(void* smem_dst, const void* gmem_src) {
    unsigned sa = (unsigned)__cvta_generic_to_shared(smem_dst);
    asm volatile("cp.async.cg.shared.global [%0], [%1], 16;" :: "r"(sa), "l"(gmem_src) : "memory");
}
__device__ __forceinline__ void cp_commit() {
    asm volatile("cp.async.commit_group;" ::: "memory");
}
template<int N> __device__ __forceinline__ void cp_wait() {
    asm volatile("cp.async.wait_group %0;" :: "n"(N) : "memory");
}

// =====================================================================
// K1: projections. BM=64 rows, 128 threads, microtile 8t x 4h x 3 mats
// (FMA-bound ratio: 48 FFMA2 per 4 LDS.128 per kk). Double-buffered.
// =====================================================================
__global__ __launch_bounds__(128) void proj_kernel(
    const float* __restrict__ x,
    const float* __restrict__ Wk, const float* __restrict__ bk,
    const float* __restrict__ Wq, const float* __restrict__ bq,
    const float* __restrict__ Wv, const float* __restrict__ bv)
{
    __shared__ float Xs[2][16][68];
    __shared__ float Ws[2][3][16][68];

    const int m0  = blockIdx.x * 64;
    const int tid = threadIdx.x;
    const int tg  = tid >> 4;   // 0..7  -> t = tg*8
    const int hg  = tid & 15;   // 0..15 -> h = hg*4

    const float* W[3] = {Wk, Wq, Wv};

    ull acc[3][8][2];
#pragma unroll
    for (int m = 0; m < 3; m++)
#pragma unroll
        for (int i = 0; i < 8; i++) { acc[m][i][0] = 0ull; acc[m][i][1] = 0ull; }

    // staging: thread handles idx = tid + it*128, it<2: r = idx>>2, c4 = (idx&3)*4
    float4 rx[2], rw[3][2];
#pragma unroll
    for (int it = 0; it < 2; it++) {
        int idx = tid + it * 128;
        int r = idx >> 2, c4 = (idx & 3) << 2;
        rx[it] = *(const float4*)(x + (size_t)(m0 + r) * D + c4);
#pragma unroll
        for (int m = 0; m < 3; m++)
            rw[m][it] = *(const float4*)(W[m] + (size_t)r * D + c4);
    }
#pragma unroll
    for (int it = 0; it < 2; it++) {
        int idx = tid + it * 128;
        int r = idx >> 2, c4 = (idx & 3) << 2;
        Xs[0][c4 + 0][r] = rx[it].x; Xs[0][c4 + 1][r] = rx[it].y;
        Xs[0][c4 + 2][r] = rx[it].z; Xs[0][c4 + 3][r] = rx[it].w;
#pragma unroll
        for (int m = 0; m < 3; m++) {
            Ws[0][m][c4 + 0][r] = rw[m][it].x; Ws[0][m][c4 + 1][r] = rw[m][it].y;
            Ws[0][m][c4 + 2][r] = rw[m][it].z; Ws[0][m][c4 + 3][r] = rw[m][it].w;
        }
    }
    __syncthreads();

    int buf = 0;
    for (int k0 = 0; k0 < D; k0 += 16) {
        const bool last = (k0 + 16 >= D);
        if (!last) {
#pragma unroll
            for (int it = 0; it < 2; it++) {
                int idx = tid + it * 128;
                int r = idx >> 2, c4 = (idx & 3) << 2;
                rx[it] = *(const float4*)(x + (size_t)(m0 + r) * D + k0 + 16 + c4);
#pragma unroll
                for (int m = 0; m < 3; m++)
                    rw[m][it] = *(const float4*)(W[m] + (size_t)r * D + k0 + 16 + c4);
            }
        }

#pragma unroll
        for (int kk = 0; kk < 16; kk++) {
            float4 a0 = *(const float4*)&Xs[buf][kk][tg * 8];
            float4 a1 = *(const float4*)&Xs[buf][kk][tg * 8 + 4];
            ull as[8] = {splat2(a0.x), splat2(a0.y), splat2(a0.z), splat2(a0.w),
                         splat2(a1.x), splat2(a1.y), splat2(a1.z), splat2(a1.w)};
#pragma unroll
            for (int m = 0; m < 3; m++) {
                float4 w = *(const float4*)&Ws[buf][m][kk][hg * 4];
                ull w0 = pack2(w.x, w.y), w1 = pack2(w.z, w.w);
#pragma unroll
                for (int i = 0; i < 8; i++) {
                    ffma2(acc[m][i][0], as[i], w0);
                    ffma2(acc[m][i][1], as[i], w1);
                }
            }
        }

        if (!last) {
            int nb = buf ^ 1;
#pragma unroll
            for (int it = 0; it < 2; it++) {
                int idx = tid + it * 128;
                int r = idx >> 2, c4 = (idx & 3) << 2;
                Xs[nb][c4 + 0][r] = rx[it].x; Xs[nb][c4 + 1][r] = rx[it].y;
                Xs[nb][c4 + 2][r] = rx[it].z; Xs[nb][c4 + 3][r] = rx[it].w;
#pragma unroll
                for (int m = 0; m < 3; m++) {
                    Ws[nb][m][c4 + 0][r] = rw[m][it].x; Ws[nb][m][c4 + 1][r] = rw[m][it].y;
                    Ws[nb][m][c4 + 2][r] = rw[m][it].z; Ws[nb][m][c4 + 3][r] = rw[m][it].w;
                }
            }
            __syncthreads();
            buf = nb;
        }
    }

    const float* bias[3] = {bk, bq, bv};
    const int b = m0 >> 11;
#pragma unroll
    for (int m = 0; m < 3; m++) {
        float4 bm = *(const float4*)(bias[m] + hg * 4);
        float bb[4] = {bm.x, bm.y, bm.z, bm.w};
#pragma unroll
        for (int i = 0; i < 8; i++) {
            int row = m0 + tg * 8 + i;
            int t   = row & (T - 1);
            float2 v0 = unpack2(acc[m][i][0]);
            float2 v1 = unpack2(acc[m][i][1]);
            float vals[4] = {v0.x + bb[0], v0.y + bb[1], v1.x + bb[2], v1.y + bb[3]};
            if (m == 0) {
#pragma unroll
                for (int j = 0; j < 4; j++)
                    g_kT[(size_t)(b * HS + hg * 4 + j) * T + t] = vals[j];
            } else if (m == 1) {
#pragma unroll
                for (int j = 0; j < 4; j++)
                    g_qT[(size_t)(b * HS + hg * 4 + j) * T + t] = vals[j];
            } else {
                *(float4*)(g_v + (size_t)row * HS + hg * 4) =
                    make_float4(vals[0], vals[1], vals[2], vals[3]);
            }
        }
    }
}

// =====================================================================
// K2a: S = 8 * q k^T.  BM=128 t, BN=256 v, 256 threads, microtile 8t x 16v.
// j-major permuted smem layout -> conflict-free 16B-lane-stride LDS.
// =====================================================================
__global__ __launch_bounds__(256, 1) void qk_kernel()
{
    extern __shared__ float4 sm4[];
    float4* Q4 = sm4;             // [64 c][32 t4] perm: idx = (x&1)*16 + (x>>1)
    float4* K4 = sm4 + 64 * 32;   // [64 c][64 v4] perm: idx = (x&3)*16 + (x>>2)

    const int v0  = blockIdx.x * 256;
    const int t0  = blockIdx.y * 128;
    const int b   = blockIdx.z;
    const int tid = threadIdx.x;

    const float4* qT4 = (const float4*)g_qT;
    const float4* kT4 = (const float4*)g_kT;

#pragma unroll
    for (int it = 0; it < 8; it++) {
        int idx = tid + it * 256;            // 0..2047
        int c = idx >> 5, x4 = idx & 31;
        int perm = ((x4 & 1) << 4) | (x4 >> 1);
        Q4[c * 32 + perm] = qT4[(size_t)(b * HS + c) * (T / 4) + (t0 >> 2) + x4];
    }
#pragma unroll
    for (int it = 0; it < 16; it++) {
        int idx = tid + it * 256;            // 0..4095
        int c = idx >> 6, x4 = idx & 63;
        int perm = ((x4 & 3) << 4) | (x4 >> 2);
        K4[c * 64 + perm] = kT4[(size_t)(b * HS + c) * (T / 4) + (v0 >> 2) + x4];
    }
    __syncthreads();

    const int tg = tid >> 4;   // t = tg*8
    const int vg = tid & 15;   // v = vg*16

    ull acc[8][8];
#pragma unroll
    for (int i = 0; i < 8; i++)
#pragma unroll
        for (int p = 0; p < 8; p++) acc[i][p] = 0ull;

#pragma unroll 4
    for (int c = 0; c < 64; c++) {
        float4 qa = Q4[c * 32 + tg];          // even t4
        float4 qb = Q4[c * 32 + 16 + tg];     // odd t4
        float4 k0 = K4[c * 64 + vg];
        float4 k1 = K4[c * 64 + 16 + vg];
        float4 k2 = K4[c * 64 + 32 + vg];
        float4 k3 = K4[c * 64 + 48 + vg];
        ull as[8] = {splat2(qa.x), splat2(qa.y), splat2(qa.z), splat2(qa.w),
                     splat2(qb.x), splat2(qb.y), splat2(qb.z), splat2(qb.w)};
        ull kp[8] = {pack2(k0.x, k0.y), pack2(k0.z, k0.w),
                     pack2(k1.x, k1.y), pack2(k1.z, k1.w),
                     pack2(k2.x, k2.y), pack2(k2.z, k2.w),
                     pack2(k3.x, k3.y), pack2(k3.z, k3.w)};
#pragma unroll
        for (int i = 0; i < 8; i++)
#pragma unroll
            for (int p = 0; p < 8; p++) ffma2(acc[i][p], as[i], kp[p]);
    }

#pragma unroll
    for (int i = 0; i < 8; i++) {
        int trow = t0 + tg * 8 + i;
        float* srow = g_s + ((size_t)(b * T + trow)) * T + v0 + vg * 16;
#pragma unroll
        for (int p = 0; p < 4; p++) {
            float2 e0 = unpack2(acc[i][2 * p]), e1 = unpack2(acc[i][2 * p + 1]);
            *(float4*)(srow + 4 * p) =
                make_float4(8.f * e0.x, 8.f * e0.y, 8.f * e1.x, 8.f * e1.y);
        }
    }
}

// =====================================================================
// K2b: S += q . rel.  grid t. 256 threads, thread = 1 v x 4 b-pairs.
// rel read ONCE via cp.async double-buffered 256-v tiles.
// =====================================================================
__global__ __launch_bounds__(256, 1) void rel_kernel(const float* __restrict__ rel)
{
    __shared__ float4 R4[2][256][16];                 // 128 KB, XOR-swizzled
    __shared__ __align__(16) ull qsP[4][64];          // [pair][c] 2 KB

    const int t   = blockIdx.x;
    const int tid = threadIdx.x;

    // stage q pairs: thread (pr = tid>>6, c = tid&63)
    {
        int pr = tid >> 6;
        int c  = tid & 63;
        float qa = g_qT[(size_t)((2 * pr + 0) * HS + c) * T + t];
        float qb = g_qT[(size_t)((2 * pr + 1) * HS + c) * T + t];
        qsP[pr][c] = pack2(qa, qb);
    }

    const int v  = tid;          // 0..255 within tile
    const int sw = tid & 15;

    const float4* relt = (const float4*)(rel + (size_t)t * T * HS);
    const size_t TT = (size_t)T * T;
    const size_t srow0 = (size_t)t * T;   // + b*TT

    const int lvv = tid >> 4;    // base row 0..15 (+16 per it)
    const int lc4 = tid & 15;

    // prefetch tile 0
#pragma unroll
    for (int it = 0; it < 16; it++) {
        int vv = lvv + it * 16;
        cp_async16(&R4[0][vv][lc4 ^ (vv & 15)], &relt[(size_t)vv * 16 + lc4]);
    }
    cp_commit();

    const int NT = T / 256;   // 8 tiles
    for (int n = 0; n < NT; n++) {
        int buf = n & 1;
        if (n + 1 < NT) {
#pragma unroll
            for (int it = 0; it < 16; it++) {
                int vv = lvv + it * 16;
                cp_async16(&R4[buf ^ 1][vv][lc4 ^ (vv & 15)],
                           &relt[(size_t)((n + 1) * 256 + vv) * 16 + lc4]);
            }
            cp_commit();
            cp_wait<1>();
        } else {
            cp_wait<0>();
        }
        __syncthreads();

        size_t si = srow0 + n * 256 + v;
        float s[8];
#pragma unroll
        for (int bb = 0; bb < 8; bb++) s[bb] = g_s[si + (size_t)bb * TT];

        ull acc[4] = {0ull, 0ull, 0ull, 0ull};
#pragma unroll
        for (int c4 = 0; c4 < 16; c4++) {
            float4 r4 = R4[buf][v][c4 ^ sw];
            ull rx = splat2(r4.x), ry = splat2(r4.y), rz = splat2(r4.z), rw = splat2(r4.w);
#pragma unroll
            for (int pr = 0; pr < 4; pr++) {
                ulonglong2 qa = *(const ulonglong2*)&qsP[pr][c4 * 4];
                ulonglong2 qb = *(const ulonglong2*)&qsP[pr][c4 * 4 + 2];
                ffma2(acc[pr], qa.x, rx);
                ffma2(acc[pr], qa.y, ry);
                ffma2(acc[pr], qb.x, rz);
                ffma2(acc[pr], qb.y, rw);
            }
        }

#pragma unroll
        for (int pr = 0; pr < 4; pr++) {
            float2 f = unpack2(acc[pr]);
            g_s[si + (size_t)(2 * pr + 0) * TT] = s[2 * pr + 0] + f.x;
            g_s[si + (size_t)(2 * pr + 1) * TT] = s[2 * pr + 1] + f.y;
        }
        __syncthreads();
    }
}

// =====================================================================
// K3: softmax + PV. 16 t rows / block, 512 threads / 16 warps, 2 CTAs/SM.
// att fp16 stride 24; PV acc packed over t (half2 -> float2 direct).
// =====================================================================
__global__ __launch_bounds__(512, 2) void soft_pv_kernel(float* __restrict__ out)
{
    extern __shared__ __align__(16) unsigned char smraw[];
    __half* attH = (__half*)smraw;          // [2048][24] fp16 = 96 KB
    float*  pout = (float*)smraw;           // reused after sync: [16][16][64] = 64 KB
    __shared__ float invl[16];

    const int t0   = blockIdx.x * 16;
    const int b    = blockIdx.y;
    const int tid  = threadIdx.x;
    const int w    = tid >> 5;      // 0..15
    const int lane = tid & 31;

    {
        const float4* srow4 = (const float4*)(g_s + ((size_t)(b * T + t0 + w)) * T);
        float m = -3.4e38f;
#pragma unroll
        for (int i = 0; i < 16; i++) {
            float4 sv = srow4[i * 32 + lane];
            m = fmaxf(m, fmaxf(fmaxf(sv.x, sv.y), fmaxf(sv.z, sv.w)));
        }
#pragma unroll
        for (int o = 16; o > 0; o >>= 1)
            m = fmaxf(m, __shfl_xor_sync(0xffffffffu, m, o));

        const float* srow = g_s + ((size_t)(b * T + t0 + w)) * T;
        float sum = 0.f;
#pragma unroll 8
        for (int i = 0; i < 64; i++) {
            int vi = i * 32 + lane;
            float e = __expf(srow[vi] - m);
            attH[vi * 24 + w] = __float2half_rn(e);
            sum += e;
        }
#pragma unroll
        for (int o = 16; o > 0; o >>= 1)
            sum += __shfl_xor_sync(0xffffffffu, sum, o);
        if (lane == 0) invl[w] = 1.f / sum;
    }
    __syncthreads();

    const int th = lane >> 4;
    const int hg = lane & 15;
    const float4* vb = (const float4*)(g_v + (size_t)b * T * HS) + hg;

    ull acc[4][4];
#pragma unroll
    for (int tp = 0; tp < 4; tp++)
#pragma unroll
        for (int h = 0; h < 4; h++) acc[tp][h] = 0ull;

    const int vbeg = w * 128;
#pragma unroll 2
    for (int v = vbeg; v < vbeg + 128; v++) {
        float4 vv = vb[(size_t)v * 16];
        ull sv[4] = {splat2(vv.x), splat2(vv.y), splat2(vv.z), splat2(vv.w)};
        uint4 raw = *(const uint4*)(attH + v * 24 + th * 8);
        const __half2* h2 = (const __half2*)&raw;
#pragma unroll
        for (int tp = 0; tp < 4; tp++) {
            float2 f = __half22float2(h2[tp]);
            ull ap = pack2(f.x, f.y);
#pragma unroll
            for (int h = 0; h < 4; h++) ffma2(acc[tp][h], ap, sv[h]);
        }
    }

    __syncthreads();

    float* pw = pout + w * 1024;
#pragma unroll
    for (int tp = 0; tp < 4; tp++) {
        int r0 = th * 8 + 2 * tp;
        float2 f0 = unpack2(acc[tp][0]), f1 = unpack2(acc[tp][1]);
        float2 f2 = unpack2(acc[tp][2]), f3 = unpack2(acc[tp][3]);
        *(float4*)(pw + r0 * 64 + hg * 4)       = make_float4(f0.x, f1.x, f2.x, f3.x);
        *(float4*)(pw + (r0 + 1) * 64 + hg * 4) = make_float4(f0.y, f1.y, f2.y, f3.y);
    }
    __syncthreads();

    {
        int tt = tid >> 5;
        int h2i = (tid & 31) * 2;
        float2 s = make_float2(0.f, 0.f);
#pragma unroll
        for (int ww = 0; ww < 16; ww++) {
            float2 p = *(float2*)(pout + ww * 1024 + tt * 64 + h2i);
            s.x += p.x; s.y += p.y;
        }
        float sc = invl[tt];
        *(float2*)(out + ((size_t)(b * T + t0 + tt)) * HS + h2i) =
            make_float2(s.x * sc, s.y * sc);
    }
}

// =====================================================================
extern "C" void kernel_launch(void* const* d_in, const int* in_sizes, int n_in,
                              void* d_out, int out_size)
{
    (void)in_sizes; (void)n_in; (void)out_size;
    const float* x   = (const float*)d_in[0];
    const float* Wk  = (const float*)d_in[1];
    const float* bk  = (const float*)d_in[2];
    const float* Wq  = (const float*)d_in[3];
    const float* bq  = (const float*)d_in[4];
    const float* Wv  = (const float*)d_in[5];
    const float* bv  = (const float*)d_in[6];
    const float* rel = (const float*)d_in[7];
    float* out = (float*)d_out;

    proj_kernel<<<(B * T) / 64, 128>>>(x, Wk, bk, Wq, bq, Wv, bv);

    const int qk_smem = (64 * 32 + 64 * 64) * sizeof(float4);   // 96 KB
    cudaFuncSetAttribute(qk_kernel, cudaFuncAttributeMaxDynamicSharedMemorySize, qk_smem);
    qk_kernel<<<dim3(T / 256, T / 128, B), 256, qk_smem>>>();

    rel_kernel<<<T, 256>>>(rel);

    const int k3_smem = 2048 * 24 * (int)sizeof(__half);  // 96 KB
    cudaFuncSetAttribute(soft_pv_kernel, cudaFuncAttributeMaxDynamicSharedMemorySize, k3_smem);
    soft_pv_kernel<<<dim3(T / 16, B), 512, k3_smem>>>(out);
}

// round 11
// speedup vs baseline: 1.4034x; 1.0308x over previous
#include <cuda_runtime.h>
#include <cuda_fp16.h>
#include <cuda_bf16.h>

#define B 8
#define T 2048
#define D 1024
#define HS 64

typedef unsigned long long ull;

// ---- device scratch ----
__device__ float g_qT[B * HS * T];                               // [b][c][t] (rel)
__device__ float g_v [B * T * HS];                               // [b][t][h]
__device__ float g_s [(size_t)B * T * T];                        // [b][t][v]
__device__ __align__(16) __nv_bfloat16 g_qhi[B * T * HS];        // [b][t][c]
__device__ __align__(16) __nv_bfloat16 g_qlo[B * T * HS];
__device__ __align__(16) __nv_bfloat16 g_khi[B * T * HS];
__device__ __align__(16) __nv_bfloat16 g_klo[B * T * HS];

// ---- packed f32x2 helpers (sm_103a FFMA2) ----
__device__ __forceinline__ ull splat2(float a) {
    ull r; asm("mov.b64 %0, {%1, %1};" : "=l"(r) : "f"(a)); return r;
}
__device__ __forceinline__ ull pack2(float x, float y) {
    ull r; asm("mov.b64 %0, {%1, %2};" : "=l"(r) : "f"(x), "f"(y)); return r;
}
__device__ __forceinline__ void ffma2(ull& d, ull a, ull b) {
    asm("fma.rn.f32x2 %0, %1, %2, %0;" : "+l"(d) : "l"(a), "l"(b));
}
__device__ __forceinline__ float2 unpack2(ull v) {
    float2 f; asm("mov.b64 {%0, %1}, %2;" : "=f"(f.x), "=f"(f.y) : "l"(v)); return f;
}
__device__ __forceinline__ void cp_async16(void* smem_dst, const void* gmem_src) {
    unsigned sa = (unsigned)__cvta_generic_to_shared(smem_dst);
    asm volatile("cp.async.cg.shared.global [%0], [%1], 16;" :: "r"(sa), "l"(gmem_src) : "memory");
}
__device__ __forceinline__ void cp_commit() {
    asm volatile("cp.async.commit_group;" ::: "memory");
}
template<int N> __device__ __forceinline__ void cp_wait() {
    asm volatile("cp.async.wait_group %0;" :: "n"(N) : "memory");
}
__device__ __forceinline__ void mma_bf16(float* d, unsigned a0, unsigned a1,
                                         unsigned a2, unsigned a3,
                                         unsigned b0, unsigned b1) {
    asm volatile(
        "mma.sync.aligned.m16n8k16.row.col.f32.bf16.bf16.f32 "
        "{%0,%1,%2,%3}, {%4,%5,%6,%7}, {%8,%9}, {%0,%1,%2,%3};"
        : "+f"(d[0]), "+f"(d[1]), "+f"(d[2]), "+f"(d[3])
        : "r"(a0), "r"(a1), "r"(a2), "r"(a3), "r"(b0), "r"(b1));
}

// =====================================================================
// K1: projections. BM=64 rows, 128 threads, microtile 8t x 4h x 3 mats.
// Emits qT fp32 (rel), v fp32, q/k hi+lo bf16 [b][t][c].
// =====================================================================
__global__ __launch_bounds__(128) void proj_kernel(
    const float* __restrict__ x,
    const float* __restrict__ Wk, const float* __restrict__ bk,
    const float* __restrict__ Wq, const float* __restrict__ bq,
    const float* __restrict__ Wv, const float* __restrict__ bv)
{
    __shared__ float Xs[2][16][68];
    __shared__ float Ws[2][3][16][68];

    const int m0  = blockIdx.x * 64;
    const int tid = threadIdx.x;
    const int tg  = tid >> 4;
    const int hg  = tid & 15;

    const float* W[3] = {Wk, Wq, Wv};

    ull acc[3][8][2];
#pragma unroll
    for (int m = 0; m < 3; m++)
#pragma unroll
        for (int i = 0; i < 8; i++) { acc[m][i][0] = 0ull; acc[m][i][1] = 0ull; }

    float4 rx[2], rw[3][2];
#pragma unroll
    for (int it = 0; it < 2; it++) {
        int idx = tid + it * 128;
        int r = idx >> 2, c4 = (idx & 3) << 2;
        rx[it] = *(const float4*)(x + (size_t)(m0 + r) * D + c4);
#pragma unroll
        for (int m = 0; m < 3; m++)
            rw[m][it] = *(const float4*)(W[m] + (size_t)r * D + c4);
    }
#pragma unroll
    for (int it = 0; it < 2; it++) {
        int idx = tid + it * 128;
        int r = idx >> 2, c4 = (idx & 3) << 2;
        Xs[0][c4 + 0][r] = rx[it].x; Xs[0][c4 + 1][r] = rx[it].y;
        Xs[0][c4 + 2][r] = rx[it].z; Xs[0][c4 + 3][r] = rx[it].w;
#pragma unroll
        for (int m = 0; m < 3; m++) {
            Ws[0][m][c4 + 0][r] = rw[m][it].x; Ws[0][m][c4 + 1][r] = rw[m][it].y;
            Ws[0][m][c4 + 2][r] = rw[m][it].z; Ws[0][m][c4 + 3][r] = rw[m][it].w;
        }
    }
    __syncthreads();

    int buf = 0;
    for (int k0 = 0; k0 < D; k0 += 16) {
        const bool last = (k0 + 16 >= D);
        if (!last) {
#pragma unroll
            for (int it = 0; it < 2; it++) {
                int idx = tid + it * 128;
                int r = idx >> 2, c4 = (idx & 3) << 2;
                rx[it] = *(const float4*)(x + (size_t)(m0 + r) * D + k0 + 16 + c4);
#pragma unroll
                for (int m = 0; m < 3; m++)
                    rw[m][it] = *(const float4*)(W[m] + (size_t)r * D + k0 + 16 + c4);
            }
        }

#pragma unroll
        for (int kk = 0; kk < 16; kk++) {
            float4 a0 = *(const float4*)&Xs[buf][kk][tg * 8];
            float4 a1 = *(const float4*)&Xs[buf][kk][tg * 8 + 4];
            ull as[8] = {splat2(a0.x), splat2(a0.y), splat2(a0.z), splat2(a0.w),
                         splat2(a1.x), splat2(a1.y), splat2(a1.z), splat2(a1.w)};
#pragma unroll
            for (int m = 0; m < 3; m++) {
                float4 w = *(const float4*)&Ws[buf][m][kk][hg * 4];
                ull w0 = pack2(w.x, w.y), w1 = pack2(w.z, w.w);
#pragma unroll
                for (int i = 0; i < 8; i++) {
                    ffma2(acc[m][i][0], as[i], w0);
                    ffma2(acc[m][i][1], as[i], w1);
                }
            }
        }

        if (!last) {
            int nb = buf ^ 1;
#pragma unroll
            for (int it = 0; it < 2; it++) {
                int idx = tid + it * 128;
                int r = idx >> 2, c4 = (idx & 3) << 2;
                Xs[nb][c4 + 0][r] = rx[it].x; Xs[nb][c4 + 1][r] = rx[it].y;
                Xs[nb][c4 + 2][r] = rx[it].z; Xs[nb][c4 + 3][r] = rx[it].w;
#pragma unroll
                for (int m = 0; m < 3; m++) {
                    Ws[nb][m][c4 + 0][r] = rw[m][it].x; Ws[nb][m][c4 + 1][r] = rw[m][it].y;
                    Ws[nb][m][c4 + 2][r] = rw[m][it].z; Ws[nb][m][c4 + 3][r] = rw[m][it].w;
                }
            }
            __syncthreads();
            buf = nb;
        }
    }

    const float* bias[3] = {bk, bq, bv};
    const int b = m0 >> 11;
#pragma unroll
    for (int m = 0; m < 3; m++) {
        float4 bm = *(const float4*)(bias[m] + hg * 4);
        float bb[4] = {bm.x, bm.y, bm.z, bm.w};
#pragma unroll
        for (int i = 0; i < 8; i++) {
            int row = m0 + tg * 8 + i;
            int t   = row & (T - 1);
            float2 v0 = unpack2(acc[m][i][0]);
            float2 v1 = unpack2(acc[m][i][1]);
            float vals[4] = {v0.x + bb[0], v0.y + bb[1], v1.x + bb[2], v1.y + bb[3]};
            if (m == 2) {
                *(float4*)(g_v + (size_t)row * HS + hg * 4) =
                    make_float4(vals[0], vals[1], vals[2], vals[3]);
            } else {
                __nv_bfloat16 hi[4], lo[4];
#pragma unroll
                for (int j = 0; j < 4; j++) {
                    hi[j] = __float2bfloat16(vals[j]);
                    lo[j] = __float2bfloat16(vals[j] - __bfloat162float(hi[j]));
                }
                size_t base = (size_t)row * HS + hg * 4;
                __nv_bfloat16* ph = (m == 0) ? g_khi : g_qhi;
                __nv_bfloat16* pl = (m == 0) ? g_klo : g_qlo;
                *(__nv_bfloat162*)(ph + base)     = __halves2bfloat162(hi[0], hi[1]);
                *(__nv_bfloat162*)(ph + base + 2) = __halves2bfloat162(hi[2], hi[3]);
                *(__nv_bfloat162*)(pl + base)     = __halves2bfloat162(lo[0], lo[1]);
                *(__nv_bfloat162*)(pl + base + 2) = __halves2bfloat162(lo[2], lo[3]);
                if (m == 1) {
#pragma unroll
                    for (int j = 0; j < 4; j++)
                        g_qT[(size_t)(b * HS + hg * 4 + j) * T + t] = vals[j];
                }
            }
        }
    }
}

// =====================================================================
// K2a: S = 8 * q k^T via mma.sync bf16 split (hh + hl + lh).
// Tile 128t x 128v x K64. 256 threads = 8 warps (4m x 2n), warp 32x64.
// Smem pitch 72 bf16 (conflict-free b32 fragment loads).
// =====================================================================
#define QKP 72
__global__ __launch_bounds__(256) void qk_mma_kernel()
{
    extern __shared__ __align__(16) unsigned char sm[];
    __nv_bfloat16* Qh = (__nv_bfloat16*)sm;          // [128][72]
    __nv_bfloat16* Ql = Qh + 128 * QKP;
    __nv_bfloat16* Kh = Ql + 128 * QKP;
    __nv_bfloat16* Kl = Kh + 128 * QKP;
    float* Sst = (float*)sm;                          // reused after mma: [128][132]

    const int tid = threadIdx.x;
    const int v0 = blockIdx.x * 128;
    const int t0 = blockIdx.y * 128;
    const int b  = blockIdx.z;

    // stage 4 tiles: 128 rows x 8 chunks of 16B each
#pragma unroll
    for (int it = 0; it < 4; it++) {
        int idx = tid + it * 256;        // 0..1023
        int row = idx >> 3, c8 = idx & 7;
        const char* qh = (const char*)(g_qhi + (size_t)(b * T + t0 + row) * HS);
        const char* ql = (const char*)(g_qlo + (size_t)(b * T + t0 + row) * HS);
        const char* kh = (const char*)(g_khi + (size_t)(b * T + v0 + row) * HS);
        const char* kl = (const char*)(g_klo + (size_t)(b * T + v0 + row) * HS);
        int off = row * (QKP * 2) + c8 * 16;
        cp_async16((char*)Qh + off, qh + c8 * 16);
        cp_async16((char*)Ql + off, ql + c8 * 16);
        cp_async16((char*)Kh + off, kh + c8 * 16);
        cp_async16((char*)Kl + off, kl + c8 * 16);
    }
    cp_commit();
    cp_wait<0>();
    __syncthreads();

    const int wid = tid >> 5, lane = tid & 31;
    const int wm = wid >> 1, wn = wid & 1;
    const int g = lane >> 2, tig = lane & 3;

    float c[2][8][4];
#pragma unroll
    for (int mt = 0; mt < 2; mt++)
#pragma unroll
        for (int nt = 0; nt < 8; nt++)
#pragma unroll
            for (int e = 0; e < 4; e++) c[mt][nt][e] = 0.f;

    const __nv_bfloat16* Ab[3] = {Qh, Qh, Ql};
    const __nv_bfloat16* Bb[3] = {Kh, Kl, Kh};

#pragma unroll
    for (int p = 0; p < 3; p++) {
        const __nv_bfloat16* A = Ab[p];
        const __nv_bfloat16* Bm = Bb[p];
#pragma unroll
        for (int ks = 0; ks < 4; ks++) {
            unsigned bf[8][2];
#pragma unroll
            for (int nt = 0; nt < 8; nt++) {
                int vrow = wn * 64 + nt * 8 + g;
                const __nv_bfloat16* bp = Bm + vrow * QKP + ks * 16 + tig * 2;
                bf[nt][0] = *(const unsigned*)(bp);
                bf[nt][1] = *(const unsigned*)(bp + 8);
            }
#pragma unroll
            for (int mt = 0; mt < 2; mt++) {
                int trow = wm * 32 + mt * 16 + g;
                const __nv_bfloat16* ap = A + trow * QKP + ks * 16 + tig * 2;
                unsigned a0 = *(const unsigned*)(ap);
                unsigned a1 = *(const unsigned*)(ap + 8 * QKP);
                unsigned a2 = *(const unsigned*)(ap + 8);
                unsigned a3 = *(const unsigned*)(ap + 8 * QKP + 8);
#pragma unroll
                for (int nt = 0; nt < 8; nt++)
                    mma_bf16(c[mt][nt], a0, a1, a2, a3, bf[nt][0], bf[nt][1]);
            }
        }
    }

    __syncthreads();   // all Q/K reads done before Sst overwrite

#pragma unroll
    for (int mt = 0; mt < 2; mt++) {
        int r = wm * 32 + mt * 16 + g;
#pragma unroll
        for (int nt = 0; nt < 8; nt++) {
            int col = wn * 64 + nt * 8 + tig * 2;
            *(float2*)&Sst[r * 132 + col] =
                make_float2(8.f * c[mt][nt][0], 8.f * c[mt][nt][1]);
            *(float2*)&Sst[(r + 8) * 132 + col] =
                make_float2(8.f * c[mt][nt][2], 8.f * c[mt][nt][3]);
        }
    }
    __syncthreads();

    // coalesced write-out: 128 rows x 32 float4
#pragma unroll
    for (int it = 0; it < 16; it++) {
        int idx = tid + it * 256;       // 0..4095
        int row = idx >> 5, c4 = idx & 31;
        float4 val = *(const float4*)&Sst[row * 132 + c4 * 4];
        *(float4*)(g_s + ((size_t)(b * T + t0 + row)) * T + v0 + c4 * 4) = val;
    }
}

// =====================================================================
// K2b: S += q . rel (unchanged from R9)
// =====================================================================
__global__ __launch_bounds__(256, 1) void rel_kernel(const float* __restrict__ rel)
{
    __shared__ float4 R4[2][256][16];
    __shared__ __align__(16) ull qsP[4][64];

    const int t   = blockIdx.x;
    const int tid = threadIdx.x;

    {
        int pr = tid >> 6;
        int c  = tid & 63;
        float qa = g_qT[(size_t)((2 * pr + 0) * HS + c) * T + t];
        float qb = g_qT[(size_t)((2 * pr + 1) * HS + c) * T + t];
        qsP[pr][c] = pack2(qa, qb);
    }

    const int v  = tid;
    const int sw = tid & 15;

    const float4* relt = (const float4*)(rel + (size_t)t * T * HS);
    const size_t TT = (size_t)T * T;
    const size_t srow0 = (size_t)t * T;

    const int lvv = tid >> 4;
    const int lc4 = tid & 15;

#pragma unroll
    for (int it = 0; it < 16; it++) {
        int vv = lvv + it * 16;
        cp_async16(&R4[0][vv][lc4 ^ (vv & 15)], &relt[(size_t)vv * 16 + lc4]);
    }
    cp_commit();

    const int NT = T / 256;
    for (int n = 0; n < NT; n++) {
        int buf = n & 1;
        if (n + 1 < NT) {
#pragma unroll
            for (int it = 0; it < 16; it++) {
                int vv = lvv + it * 16;
                cp_async16(&R4[buf ^ 1][vv][lc4 ^ (vv & 15)],
                           &relt[(size_t)((n + 1) * 256 + vv) * 16 + lc4]);
            }
            cp_commit();
            cp_wait<1>();
        } else {
            cp_wait<0>();
        }
        __syncthreads();

        size_t si = srow0 + n * 256 + v;
        float s[8];
#pragma unroll
        for (int bb = 0; bb < 8; bb++) s[bb] = g_s[si + (size_t)bb * TT];

        ull acc[4] = {0ull, 0ull, 0ull, 0ull};
#pragma unroll
        for (int c4 = 0; c4 < 16; c4++) {
            float4 r4 = R4[buf][v][c4 ^ sw];
            ull rx = splat2(r4.x), ry = splat2(r4.y), rz = splat2(r4.z), rw = splat2(r4.w);
#pragma unroll
            for (int pr = 0; pr < 4; pr++) {
                ulonglong2 qa = *(const ulonglong2*)&qsP[pr][c4 * 4];
                ulonglong2 qb = *(const ulonglong2*)&qsP[pr][c4 * 4 + 2];
                ffma2(acc[pr], qa.x, rx);
                ffma2(acc[pr], qa.y, ry);
                ffma2(acc[pr], qb.x, rz);
                ffma2(acc[pr], qb.y, rw);
            }
        }

#pragma unroll
        for (int pr = 0; pr < 4; pr++) {
            float2 f = unpack2(acc[pr]);
            g_s[si + (size_t)(2 * pr + 0) * TT] = s[2 * pr + 0] + f.x;
            g_s[si + (size_t)(2 * pr + 1) * TT] = s[2 * pr + 1] + f.y;
        }
        __syncthreads();
    }
}

// =====================================================================
// K3: softmax + PV (unchanged from R9)
// =====================================================================
__global__ __launch_bounds__(512, 2) void soft_pv_kernel(float* __restrict__ out)
{
    extern __shared__ __align__(16) unsigned char smraw[];
    __half* attH = (__half*)smraw;
    float*  pout = (float*)smraw;
    __shared__ float invl[16];

    const int t0   = blockIdx.x * 16;
    const int b    = blockIdx.y;
    const int tid  = threadIdx.x;
    const int w    = tid >> 5;
    const int lane = tid & 31;

    {
        const float4* srow4 = (const float4*)(g_s + ((size_t)(b * T + t0 + w)) * T);
        float m = -3.4e38f;
#pragma unroll
        for (int i = 0; i < 16; i++) {
            float4 sv = srow4[i * 32 + lane];
            m = fmaxf(m, fmaxf(fmaxf(sv.x, sv.y), fmaxf(sv.z, sv.w)));
        }
#pragma unroll
        for (int o = 16; o > 0; o >>= 1)
            m = fmaxf(m, __shfl_xor_sync(0xffffffffu, m, o));

        const float* srow = g_s + ((size_t)(b * T + t0 + w)) * T;
        float sum = 0.f;
#pragma unroll 8
        for (int i = 0; i < 64; i++) {
            int vi = i * 32 + lane;
            float e = __expf(srow[vi] - m);
            attH[vi * 24 + w] = __float2half_rn(e);
            sum += e;
        }
#pragma unroll
        for (int o = 16; o > 0; o >>= 1)
            sum += __shfl_xor_sync(0xffffffffu, sum, o);
        if (lane == 0) invl[w] = 1.f / sum;
    }
    __syncthreads();

    const int th = lane >> 4;
    const int hg = lane & 15;
    const float4* vb = (const float4*)(g_v + (size_t)b * T * HS) + hg;

    ull acc[4][4];
#pragma unroll
    for (int tp = 0; tp < 4; tp++)
#pragma unroll
        for (int h = 0; h < 4; h++) acc[tp][h] = 0ull;

    const int vbeg = w * 128;
#pragma unroll 2
    for (int v = vbeg; v < vbeg + 128; v++) {
        float4 vv = vb[(size_t)v * 16];
        ull sv[4] = {splat2(vv.x), splat2(vv.y), splat2(vv.z), splat2(vv.w)};
        uint4 raw = *(const uint4*)(attH + v * 24 + th * 8);
        const __half2* h2 = (const __half2*)&raw;
#pragma unroll
        for (int tp = 0; tp < 4; tp++) {
            float2 f = __half22float2(h2[tp]);
            ull ap = pack2(f.x, f.y);
#pragma unroll
            for (int h = 0; h < 4; h++) ffma2(acc[tp][h], ap, sv[h]);
        }
    }

    __syncthreads();

    float* pw = pout + w * 1024;
#pragma unroll
    for (int tp = 0; tp < 4; tp++) {
        int r0 = th * 8 + 2 * tp;
        float2 f0 = unpack2(acc[tp][0]), f1 = unpack2(acc[tp][1]);
        float2 f2 = unpack2(acc[tp][2]), f3 = unpack2(acc[tp][3]);
        *(float4*)(pw + r0 * 64 + hg * 4)       = make_float4(f0.x, f1.x, f2.x, f3.x);
        *(float4*)(pw + (r0 + 1) * 64 + hg * 4) = make_float4(f0.y, f1.y, f2.y, f3.y);
    }
    __syncthreads();

    {
        int tt = tid >> 5;
        int h2i = (tid & 31) * 2;
        float2 s = make_float2(0.f, 0.f);
#pragma unroll
        for (int ww = 0; ww < 16; ww++) {
            float2 p = *(float2*)(pout + ww * 1024 + tt * 64 + h2i);
            s.x += p.x; s.y += p.y;
        }
        float sc = invl[tt];
        *(float2*)(out + ((size_t)(b * T + t0 + tt)) * HS + h2i) =
            make_float2(s.x * sc, s.y * sc);
    }
}

// =====================================================================
extern "C" void kernel_launch(void* const* d_in, const int* in_sizes, int n_in,
                              void* d_out, int out_size)
{
    (void)in_sizes; (void)n_in; (void)out_size;
    const float* x   = (const float*)d_in[0];
    const float* Wk  = (const float*)d_in[1];
    const float* bk  = (const float*)d_in[2];
    const float* Wq  = (const float*)d_in[3];
    const float* bq  = (const float*)d_in[4];
    const float* Wv  = (const float*)d_in[5];
    const float* bv  = (const float*)d_in[6];
    const float* rel = (const float*)d_in[7];
    float* out = (float*)d_out;

    proj_kernel<<<(B * T) / 64, 128>>>(x, Wk, bk, Wq, bq, Wv, bv);

    const int qk_smem = 4 * 128 * QKP * (int)sizeof(__nv_bfloat16);   // 73728
    cudaFuncSetAttribute(qk_mma_kernel, cudaFuncAttributeMaxDynamicSharedMemorySize, qk_smem);
    qk_mma_kernel<<<dim3(T / 128, T / 128, B), 256, qk_smem>>>();

    rel_kernel<<<T, 256>>>(rel);

    const int k3_smem = 2048 * 24 * (int)sizeof(__half);
    cudaFuncSetAttribute(soft_pv_kernel, cudaFuncAttributeMaxDynamicSharedMemorySize, k3_smem);
    soft_pv_kernel<<<dim3(T / 16, B), 512, k3_smem>>>(out);
}

// round 12
// speedup vs baseline: 1.4426x; 1.0280x over previous
#include <cuda_runtime.h>
#include <cuda_fp16.h>
#include <cuda_bf16.h>

#define B 8
#define T 2048
#define D 1024
#define HS 64

typedef unsigned long long ull;

// ---- device scratch ----
__device__ float g_qT[B * HS * T];                               // [b][c][t] (rel)
__device__ float g_s [(size_t)B * T * T];                        // [b][t][v]
__device__ __align__(16) __nv_bfloat16 g_qhi[B * T * HS];        // [b][t][c]
__device__ __align__(16) __nv_bfloat16 g_qlo[B * T * HS];
__device__ __align__(16) __nv_bfloat16 g_khi[B * T * HS];
__device__ __align__(16) __nv_bfloat16 g_klo[B * T * HS];
__device__ __align__(16) __half g_vthi[B * HS * T];              // [b][h][t]
__device__ __align__(16) __half g_vtlo[B * HS * T];

// ---- packed f32x2 helpers ----
__device__ __forceinline__ ull splat2(float a) {
    ull r; asm("mov.b64 %0, {%1, %1};" : "=l"(r) : "f"(a)); return r;
}
__device__ __forceinline__ ull pack2(float x, float y) {
    ull r; asm("mov.b64 %0, {%1, %2};" : "=l"(r) : "f"(x), "f"(y)); return r;
}
__device__ __forceinline__ void ffma2(ull& d, ull a, ull b) {
    asm("fma.rn.f32x2 %0, %1, %2, %0;" : "+l"(d) : "l"(a), "l"(b));
}
__device__ __forceinline__ float2 unpack2(ull v) {
    float2 f; asm("mov.b64 {%0, %1}, %2;" : "=f"(f.x), "=f"(f.y) : "l"(v)); return f;
}
__device__ __forceinline__ void cp_async16(void* smem_dst, const void* gmem_src) {
    unsigned sa = (unsigned)__cvta_generic_to_shared(smem_dst);
    asm volatile("cp.async.cg.shared.global [%0], [%1], 16;" :: "r"(sa), "l"(gmem_src) : "memory");
}
__device__ __forceinline__ void cp_commit() {
    asm volatile("cp.async.commit_group;" ::: "memory");
}
template<int N> __device__ __forceinline__ void cp_wait() {
    asm volatile("cp.async.wait_group %0;" :: "n"(N) : "memory");
}
__device__ __forceinline__ void mma_bf16(float* d, unsigned a0, unsigned a1,
                                         unsigned a2, unsigned a3,
                                         unsigned b0, unsigned b1) {
    asm volatile(
        "mma.sync.aligned.m16n8k16.row.col.f32.bf16.bf16.f32 "
        "{%0,%1,%2,%3}, {%4,%5,%6,%7}, {%8,%9}, {%0,%1,%2,%3};"
        : "+f"(d[0]), "+f"(d[1]), "+f"(d[2]), "+f"(d[3])
        : "r"(a0), "r"(a1), "r"(a2), "r"(a3), "r"(b0), "r"(b1));
}
__device__ __forceinline__ void mma_f16(float* d, unsigned a0, unsigned a1,
                                        unsigned a2, unsigned a3,
                                        unsigned b0, unsigned b1) {
    asm volatile(
        "mma.sync.aligned.m16n8k16.row.col.f32.f16.f16.f32 "
        "{%0,%1,%2,%3}, {%4,%5,%6,%7}, {%8,%9}, {%0,%1,%2,%3};"
        : "+f"(d[0]), "+f"(d[1]), "+f"(d[2]), "+f"(d[3])
        : "r"(a0), "r"(a1), "r"(a2), "r"(a3), "r"(b0), "r"(b1));
}

// =====================================================================
// K1: projections. BM=64 rows, 128 threads, microtile 8t x 4h x 3 mats.
// Emits qT fp32 (rel), q/k hi+lo bf16 [b][t][c], V^T hi+lo fp16 [b][h][t].
// =====================================================================
__global__ __launch_bounds__(128) void proj_kernel(
    const float* __restrict__ x,
    const float* __restrict__ Wk, const float* __restrict__ bk,
    const float* __restrict__ Wq, const float* __restrict__ bq,
    const float* __restrict__ Wv, const float* __restrict__ bv)
{
    __shared__ float Xs[2][16][68];
    __shared__ float Ws[2][3][16][68];

    const int m0  = blockIdx.x * 64;
    const int tid = threadIdx.x;
    const int tg  = tid >> 4;
    const int hg  = tid & 15;

    const float* W[3] = {Wk, Wq, Wv};

    ull acc[3][8][2];
#pragma unroll
    for (int m = 0; m < 3; m++)
#pragma unroll
        for (int i = 0; i < 8; i++) { acc[m][i][0] = 0ull; acc[m][i][1] = 0ull; }

    float4 rx[2], rw[3][2];
#pragma unroll
    for (int it = 0; it < 2; it++) {
        int idx = tid + it * 128;
        int r = idx >> 2, c4 = (idx & 3) << 2;
        rx[it] = *(const float4*)(x + (size_t)(m0 + r) * D + c4);
#pragma unroll
        for (int m = 0; m < 3; m++)
            rw[m][it] = *(const float4*)(W[m] + (size_t)r * D + c4);
    }
#pragma unroll
    for (int it = 0; it < 2; it++) {
        int idx = tid + it * 128;
        int r = idx >> 2, c4 = (idx & 3) << 2;
        Xs[0][c4 + 0][r] = rx[it].x; Xs[0][c4 + 1][r] = rx[it].y;
        Xs[0][c4 + 2][r] = rx[it].z; Xs[0][c4 + 3][r] = rx[it].w;
#pragma unroll
        for (int m = 0; m < 3; m++) {
            Ws[0][m][c4 + 0][r] = rw[m][it].x; Ws[0][m][c4 + 1][r] = rw[m][it].y;
            Ws[0][m][c4 + 2][r] = rw[m][it].z; Ws[0][m][c4 + 3][r] = rw[m][it].w;
        }
    }
    __syncthreads();

    int buf = 0;
    for (int k0 = 0; k0 < D; k0 += 16) {
        const bool last = (k0 + 16 >= D);
        if (!last) {
#pragma unroll
            for (int it = 0; it < 2; it++) {
                int idx = tid + it * 128;
                int r = idx >> 2, c4 = (idx & 3) << 2;
                rx[it] = *(const float4*)(x + (size_t)(m0 + r) * D + k0 + 16 + c4);
#pragma unroll
                for (int m = 0; m < 3; m++)
                    rw[m][it] = *(const float4*)(W[m] + (size_t)r * D + k0 + 16 + c4);
            }
        }

#pragma unroll
        for (int kk = 0; kk < 16; kk++) {
            float4 a0 = *(const float4*)&Xs[buf][kk][tg * 8];
            float4 a1 = *(const float4*)&Xs[buf][kk][tg * 8 + 4];
            ull as[8] = {splat2(a0.x), splat2(a0.y), splat2(a0.z), splat2(a0.w),
                         splat2(a1.x), splat2(a1.y), splat2(a1.z), splat2(a1.w)};
#pragma unroll
            for (int m = 0; m < 3; m++) {
                float4 w = *(const float4*)&Ws[buf][m][kk][hg * 4];
                ull w0 = pack2(w.x, w.y), w1 = pack2(w.z, w.w);
#pragma unroll
                for (int i = 0; i < 8; i++) {
                    ffma2(acc[m][i][0], as[i], w0);
                    ffma2(acc[m][i][1], as[i], w1);
                }
            }
        }

        if (!last) {
            int nb = buf ^ 1;
#pragma unroll
            for (int it = 0; it < 2; it++) {
                int idx = tid + it * 128;
                int r = idx >> 2, c4 = (idx & 3) << 2;
                Xs[nb][c4 + 0][r] = rx[it].x; Xs[nb][c4 + 1][r] = rx[it].y;
                Xs[nb][c4 + 2][r] = rx[it].z; Xs[nb][c4 + 3][r] = rx[it].w;
#pragma unroll
                for (int m = 0; m < 3; m++) {
                    Ws[nb][m][c4 + 0][r] = rw[m][it].x; Ws[nb][m][c4 + 1][r] = rw[m][it].y;
                    Ws[nb][m][c4 + 2][r] = rw[m][it].z; Ws[nb][m][c4 + 3][r] = rw[m][it].w;
                }
            }
            __syncthreads();
            buf = nb;
        }
    }

    const float* bias[3] = {bk, bq, bv};
    const int b = m0 >> 11;
#pragma unroll
    for (int m = 0; m < 3; m++) {
        float4 bm = *(const float4*)(bias[m] + hg * 4);
        float bb[4] = {bm.x, bm.y, bm.z, bm.w};
#pragma unroll
        for (int i = 0; i < 8; i++) {
            int row = m0 + tg * 8 + i;
            int t   = row & (T - 1);
            float2 v0 = unpack2(acc[m][i][0]);
            float2 v1 = unpack2(acc[m][i][1]);
            float vals[4] = {v0.x + bb[0], v0.y + bb[1], v1.x + bb[2], v1.y + bb[3]};
            if (m == 2) {
                // V^T fp16 hi/lo [b][h][t]
#pragma unroll
                for (int j = 0; j < 4; j++) {
                    __half hi = __float2half_rn(vals[j]);
                    __half lo = __float2half_rn(vals[j] - __half2float(hi));
                    size_t a = (size_t)(b * HS + hg * 4 + j) * T + t;
                    g_vthi[a] = hi;
                    g_vtlo[a] = lo;
                }
            } else {
                __nv_bfloat16 hi[4], lo[4];
#pragma unroll
                for (int j = 0; j < 4; j++) {
                    hi[j] = __float2bfloat16(vals[j]);
                    lo[j] = __float2bfloat16(vals[j] - __bfloat162float(hi[j]));
                }
                size_t base = (size_t)row * HS + hg * 4;
                __nv_bfloat16* ph = (m == 0) ? g_khi : g_qhi;
                __nv_bfloat16* pl = (m == 0) ? g_klo : g_qlo;
                *(__nv_bfloat162*)(ph + base)     = __halves2bfloat162(hi[0], hi[1]);
                *(__nv_bfloat162*)(ph + base + 2) = __halves2bfloat162(hi[2], hi[3]);
                *(__nv_bfloat162*)(pl + base)     = __halves2bfloat162(lo[0], lo[1]);
                *(__nv_bfloat162*)(pl + base + 2) = __halves2bfloat162(lo[2], lo[3]);
                if (m == 1) {
#pragma unroll
                    for (int j = 0; j < 4; j++)
                        g_qT[(size_t)(b * HS + hg * 4 + j) * T + t] = vals[j];
                }
            }
        }
    }
}

// =====================================================================
// K2a: S = 8 * q k^T via mma.sync bf16 split (unchanged from R11)
// =====================================================================
#define QKP 72
__global__ __launch_bounds__(256) void qk_mma_kernel()
{
    extern __shared__ __align__(16) unsigned char sm[];
    __nv_bfloat16* Qh = (__nv_bfloat16*)sm;
    __nv_bfloat16* Ql = Qh + 128 * QKP;
    __nv_bfloat16* Kh = Ql + 128 * QKP;
    __nv_bfloat16* Kl = Kh + 128 * QKP;
    float* Sst = (float*)sm;

    const int tid = threadIdx.x;
    const int v0 = blockIdx.x * 128;
    const int t0 = blockIdx.y * 128;
    const int b  = blockIdx.z;

#pragma unroll
    for (int it = 0; it < 4; it++) {
        int idx = tid + it * 256;
        int row = idx >> 3, c8 = idx & 7;
        const char* qh = (const char*)(g_qhi + (size_t)(b * T + t0 + row) * HS);
        const char* ql = (const char*)(g_qlo + (size_t)(b * T + t0 + row) * HS);
        const char* kh = (const char*)(g_khi + (size_t)(b * T + v0 + row) * HS);
        const char* kl = (const char*)(g_klo + (size_t)(b * T + v0 + row) * HS);
        int off = row * (QKP * 2) + c8 * 16;
        cp_async16((char*)Qh + off, qh + c8 * 16);
        cp_async16((char*)Ql + off, ql + c8 * 16);
        cp_async16((char*)Kh + off, kh + c8 * 16);
        cp_async16((char*)Kl + off, kl + c8 * 16);
    }
    cp_commit();
    cp_wait<0>();
    __syncthreads();

    const int wid = tid >> 5, lane = tid & 31;
    const int wm = wid >> 1, wn = wid & 1;
    const int g = lane >> 2, tig = lane & 3;

    float c[2][8][4];
#pragma unroll
    for (int mt = 0; mt < 2; mt++)
#pragma unroll
        for (int nt = 0; nt < 8; nt++)
#pragma unroll
            for (int e = 0; e < 4; e++) c[mt][nt][e] = 0.f;

    const __nv_bfloat16* Ab[3] = {Qh, Qh, Ql};
    const __nv_bfloat16* Bb[3] = {Kh, Kl, Kh};

#pragma unroll
    for (int p = 0; p < 3; p++) {
        const __nv_bfloat16* A = Ab[p];
        const __nv_bfloat16* Bm = Bb[p];
#pragma unroll
        for (int ks = 0; ks < 4; ks++) {
            unsigned bf[8][2];
#pragma unroll
            for (int nt = 0; nt < 8; nt++) {
                int vrow = wn * 64 + nt * 8 + g;
                const __nv_bfloat16* bp = Bm + vrow * QKP + ks * 16 + tig * 2;
                bf[nt][0] = *(const unsigned*)(bp);
                bf[nt][1] = *(const unsigned*)(bp + 8);
            }
#pragma unroll
            for (int mt = 0; mt < 2; mt++) {
                int trow = wm * 32 + mt * 16 + g;
                const __nv_bfloat16* ap = A + trow * QKP + ks * 16 + tig * 2;
                unsigned a0 = *(const unsigned*)(ap);
                unsigned a1 = *(const unsigned*)(ap + 8 * QKP);
                unsigned a2 = *(const unsigned*)(ap + 8);
                unsigned a3 = *(const unsigned*)(ap + 8 * QKP + 8);
#pragma unroll
                for (int nt = 0; nt < 8; nt++)
                    mma_bf16(c[mt][nt], a0, a1, a2, a3, bf[nt][0], bf[nt][1]);
            }
        }
    }

    __syncthreads();

#pragma unroll
    for (int mt = 0; mt < 2; mt++) {
        int r = wm * 32 + mt * 16 + g;
#pragma unroll
        for (int nt = 0; nt < 8; nt++) {
            int col = wn * 64 + nt * 8 + tig * 2;
            *(float2*)&Sst[r * 132 + col] =
                make_float2(8.f * c[mt][nt][0], 8.f * c[mt][nt][1]);
            *(float2*)&Sst[(r + 8) * 132 + col] =
                make_float2(8.f * c[mt][nt][2], 8.f * c[mt][nt][3]);
        }
    }
    __syncthreads();

#pragma unroll
    for (int it = 0; it < 16; it++) {
        int idx = tid + it * 256;
        int row = idx >> 5, c4 = idx & 31;
        float4 val = *(const float4*)&Sst[row * 132 + c4 * 4];
        *(float4*)(g_s + ((size_t)(b * T + t0 + row)) * T + v0 + c4 * 4) = val;
    }
}

// =====================================================================
// K2b: S += q . rel (unchanged from R11)
// =====================================================================
__global__ __launch_bounds__(256, 1) void rel_kernel(const float* __restrict__ rel)
{
    __shared__ float4 R4[2][256][16];
    __shared__ __align__(16) ull qsP[4][64];

    const int t   = blockIdx.x;
    const int tid = threadIdx.x;

    {
        int pr = tid >> 6;
        int c  = tid & 63;
        float qa = g_qT[(size_t)((2 * pr + 0) * HS + c) * T + t];
        float qb = g_qT[(size_t)((2 * pr + 1) * HS + c) * T + t];
        qsP[pr][c] = pack2(qa, qb);
    }

    const int v  = tid;
    const int sw = tid & 15;

    const float4* relt = (const float4*)(rel + (size_t)t * T * HS);
    const size_t TT = (size_t)T * T;
    const size_t srow0 = (size_t)t * T;

    const int lvv = tid >> 4;
    const int lc4 = tid & 15;

#pragma unroll
    for (int it = 0; it < 16; it++) {
        int vv = lvv + it * 16;
        cp_async16(&R4[0][vv][lc4 ^ (vv & 15)], &relt[(size_t)vv * 16 + lc4]);
    }
    cp_commit();

    const int NT = T / 256;
    for (int n = 0; n < NT; n++) {
        int buf = n & 1;
        if (n + 1 < NT) {
#pragma unroll
            for (int it = 0; it < 16; it++) {
                int vv = lvv + it * 16;
                cp_async16(&R4[buf ^ 1][vv][lc4 ^ (vv & 15)],
                           &relt[(size_t)((n + 1) * 256 + vv) * 16 + lc4]);
            }
            cp_commit();
            cp_wait<1>();
        } else {
            cp_wait<0>();
        }
        __syncthreads();

        size_t si = srow0 + n * 256 + v;
        float s[8];
#pragma unroll
        for (int bb = 0; bb < 8; bb++) s[bb] = g_s[si + (size_t)bb * TT];

        ull acc[4] = {0ull, 0ull, 0ull, 0ull};
#pragma unroll
        for (int c4 = 0; c4 < 16; c4++) {
            float4 r4 = R4[buf][v][c4 ^ sw];
            ull rx = splat2(r4.x), ry = splat2(r4.y), rz = splat2(r4.z), rw = splat2(r4.w);
#pragma unroll
            for (int pr = 0; pr < 4; pr++) {
                ulonglong2 qa = *(const ulonglong2*)&qsP[pr][c4 * 4];
                ulonglong2 qb = *(const ulonglong2*)&qsP[pr][c4 * 4 + 2];
                ffma2(acc[pr], qa.x, rx);
                ffma2(acc[pr], qa.y, ry);
                ffma2(acc[pr], qb.x, rz);
                ffma2(acc[pr], qb.y, rw);
            }
        }

#pragma unroll
        for (int pr = 0; pr < 4; pr++) {
            float2 f = unpack2(acc[pr]);
            g_s[si + (size_t)(2 * pr + 0) * TT] = s[2 * pr + 0] + f.x;
            g_s[si + (size_t)(2 * pr + 1) * TT] = s[2 * pr + 1] + f.y;
        }
        __syncthreads();
    }
}

// =====================================================================
// K3: softmax + PV via fp16 HMMA.
// 16 t / block, 512 threads / 16 warps, 2 CTAs/SM.
// att fp16 [16t][2056v]. V^T fp16 hi/lo cp.async-staged (64-v chunks,
// double buffered). Warp = (h-tile 0..7, v-half 0..1): D = one 16x8 tile.
// =====================================================================
#define ATP 2056
#define VTP 72
__global__ __launch_bounds__(512, 2) void soft_pv_kernel(float* __restrict__ out)
{
    extern __shared__ __align__(16) unsigned char smraw[];
    __half* attH = (__half*)smraw;                       // 16*2056*2 = 65792
    __half* Vts  = (__half*)(smraw + 65792);             // [2buf][2 hi/lo][64][72] = 36864
    float*  pout = (float*)(smraw + 65792 + 36864);      // [16w][16t][8h] = 8192
    __shared__ float invl[16];

    const int t0   = blockIdx.x * 16;
    const int b    = blockIdx.y;
    const int tid  = threadIdx.x;
    const int w    = tid >> 5;
    const int lane = tid & 31;
    const int g    = lane >> 2;
    const int tig  = lane & 3;

    // ---- softmax of row w (one warp per row) ----
    {
        const float4* srow4 = (const float4*)(g_s + ((size_t)(b * T + t0 + w)) * T);
        float m = -3.4e38f;
#pragma unroll
        for (int i = 0; i < 16; i++) {
            float4 sv = srow4[i * 32 + lane];
            m = fmaxf(m, fmaxf(fmaxf(sv.x, sv.y), fmaxf(sv.z, sv.w)));
        }
#pragma unroll
        for (int o = 16; o > 0; o >>= 1)
            m = fmaxf(m, __shfl_xor_sync(0xffffffffu, m, o));

        const float* srow = g_s + ((size_t)(b * T + t0 + w)) * T;
        float sum = 0.f;
#pragma unroll 8
        for (int i = 0; i < 64; i++) {
            int vi = i * 32 + lane;
            float e = __expf(srow[vi] - m);
            attH[w * ATP + vi] = __float2half_rn(e);
            sum += e;
        }
#pragma unroll
        for (int o = 16; o > 0; o >>= 1)
            sum += __shfl_xor_sync(0xffffffffu, sum, o);
        if (lane == 0) invl[w] = 1.f / sum;
    }

    // ---- PV via HMMA ----
    const int hf = w & 1;        // v-half of chunk
    const int ht = w >> 1;       // h-tile 0..7
    float d[4] = {0.f, 0.f, 0.f, 0.f};

    // stage map: sel = tid>>8 (hi/lo), hh = (tid&255)>>2, cpair = tid&3 -> 2 x 16B
    const int sel   = tid >> 8;
    const int hh    = (tid & 255) >> 2;
    const int cpair = tid & 3;
    const __half* vsrc = (sel ? g_vtlo : g_vthi) + (size_t)(b * HS + hh) * T;

    // prefetch chunk 0 into buf 0
#pragma unroll
    for (int u = 0; u < 2; u++) {
        int c16 = cpair * 2 + u;                 // 0..7 (8 x 8 halves = 64 v)
        cp_async16(&Vts[((0 * 2 + sel) * 64 + hh) * VTP + c16 * 8], vsrc + c16 * 8);
    }
    cp_commit();

    const int NT = T / 64;   // 32 chunks
    for (int ck = 0; ck < NT; ck++) {
        const int buf = ck & 1;
        cp_wait<0>();
        __syncthreads();     // chunk ck ready; prior chunk's reads complete; (ck=0: attH visible)

        if (ck + 1 < NT) {
            const __half* src2 = vsrc + (ck + 1) * 64;
#pragma unroll
            for (int u = 0; u < 2; u++) {
                int c16 = cpair * 2 + u;
                cp_async16(&Vts[(((buf ^ 1) * 2 + sel) * 64 + hh) * VTP + c16 * 8],
                           src2 + c16 * 8);
            }
            cp_commit();
        }

        const int v0 = ck * 64;
#pragma unroll
        for (int ks = 0; ks < 2; ks++) {
            int vloc = hf * 32 + ks * 16;
            const __half* ap = attH + g * ATP + v0 + vloc + 2 * tig;
            unsigned a0 = *(const unsigned*)(ap);
            unsigned a1 = *(const unsigned*)(ap + 8 * ATP);
            unsigned a2 = *(const unsigned*)(ap + 8);
            unsigned a3 = *(const unsigned*)(ap + 8 * ATP + 8);
            const __half* bh = &Vts[((buf * 2 + 0) * 64 + ht * 8 + g) * VTP + vloc + 2 * tig];
            mma_f16(d, a0, a1, a2, a3,
                    *(const unsigned*)bh, *(const unsigned*)(bh + 8));
            const __half* bl = &Vts[((buf * 2 + 1) * 64 + ht * 8 + g) * VTP + vloc + 2 * tig];
            mma_f16(d, a0, a1, a2, a3,
                    *(const unsigned*)bl, *(const unsigned*)(bl + 8));
        }
    }

    // ---- cross-warp reduce (pairs sharing ht) ----
    {
        float* pw = pout + w * 128;
        *(float2*)&pw[g * 8 + 2 * tig]       = make_float2(d[0], d[1]);
        *(float2*)&pw[(g + 8) * 8 + 2 * tig] = make_float2(d[2], d[3]);
    }
    __syncthreads();

    {
        int t   = tid >> 5;            // 0..15
        int hl  = tid & 31;            // h = 2*hl
        int ht2 = hl >> 2;             // h-tile
        int hloc = (hl & 3) * 2;
        float2 p0 = *(const float2*)&pout[(ht2 * 2 + 0) * 128 + t * 8 + hloc];
        float2 p1 = *(const float2*)&pout[(ht2 * 2 + 1) * 128 + t * 8 + hloc];
        float sc = invl[t];
        *(float2*)(out + ((size_t)(b * T + t0 + t)) * HS + hl * 2) =
            make_float2((p0.x + p1.x) * sc, (p0.y + p1.y) * sc);
    }
}

// =====================================================================
extern "C" void kernel_launch(void* const* d_in, const int* in_sizes, int n_in,
                              void* d_out, int out_size)
{
    (void)in_sizes; (void)n_in; (void)out_size;
    const float* x   = (const float*)d_in[0];
    const float* Wk  = (const float*)d_in[1];
    const float* bk  = (const float*)d_in[2];
    const float* Wq  = (const float*)d_in[3];
    const float* bq  = (const float*)d_in[4];
    const float* Wv  = (const float*)d_in[5];
    const float* bv  = (const float*)d_in[6];
    const float* rel = (const float*)d_in[7];
    float* out = (float*)d_out;

    proj_kernel<<<(B * T) / 64, 128>>>(x, Wk, bk, Wq, bq, Wv, bv);

    const int qk_smem = 4 * 128 * QKP * (int)sizeof(__nv_bfloat16);
    cudaFuncSetAttribute(qk_mma_kernel, cudaFuncAttributeMaxDynamicSharedMemorySize, qk_smem);
    qk_mma_kernel<<<dim3(T / 128, T / 128, B), 256, qk_smem>>>();

    rel_kernel<<<T, 256>>>(rel);

    const int k3_smem = 65792 + 36864 + 8192;   // 110848
    cudaFuncSetAttribute(soft_pv_kernel, cudaFuncAttributeMaxDynamicSharedMemorySize, k3_smem);
    soft_pv_kernel<<<dim3(T / 16, B), 512, k3_smem>>>(out);
}

// round 13
// speedup vs baseline: 1.6912x; 1.1723x over previous
#include <cuda_runtime.h>
#include <cuda_fp16.h>
#include <cuda_bf16.h>

#define B 8
#define T 2048
#define D 1024
#define HS 64

typedef unsigned long long ull;

// ---- device scratch ----
__device__ float g_qT[B * HS * T];                               // [b][c][t] (rel)
__device__ float g_s [(size_t)B * T * T];                        // [b][t][v]
__device__ __align__(16) __nv_bfloat16 g_qhi[B * T * HS];        // [b][t][c]
__device__ __align__(16) __nv_bfloat16 g_qlo[B * T * HS];
__device__ __align__(16) __nv_bfloat16 g_khi[B * T * HS];
__device__ __align__(16) __nv_bfloat16 g_klo[B * T * HS];
__device__ __align__(16) __half g_vthi[B * HS * T];              // [b][h][t]
__device__ __align__(16) __half g_vtlo[B * HS * T];
__device__ __align__(16) __nv_bfloat16 g_xhi[B * T * D];         // [row][c]
__device__ __align__(16) __nv_bfloat16 g_xlo[B * T * D];
__device__ __align__(16) __nv_bfloat16 g_whi[3 * HS * D];        // [mat*64+h][c]
__device__ __align__(16) __nv_bfloat16 g_wlo[3 * HS * D];

// ---- packed f32x2 helpers ----
__device__ __forceinline__ ull splat2(float a) {
    ull r; asm("mov.b64 %0, {%1, %1};" : "=l"(r) : "f"(a)); return r;
}
__device__ __forceinline__ ull pack2(float x, float y) {
    ull r; asm("mov.b64 %0, {%1, %2};" : "=l"(r) : "f"(x), "f"(y)); return r;
}
__device__ __forceinline__ void ffma2(ull& d, ull a, ull b) {
    asm("fma.rn.f32x2 %0, %1, %2, %0;" : "+l"(d) : "l"(a), "l"(b));
}
__device__ __forceinline__ float2 unpack2(ull v) {
    float2 f; asm("mov.b64 {%0, %1}, %2;" : "=f"(f.x), "=f"(f.y) : "l"(v)); return f;
}
__device__ __forceinline__ void cp_async16(void* smem_dst, const void* gmem_src) {
    unsigned sa = (unsigned)__cvta_generic_to_shared(smem_dst);
    asm volatile("cp.async.cg.shared.global [%0], [%1], 16;" :: "r"(sa), "l"(gmem_src) : "memory");
}
__device__ __forceinline__ void cp_commit() {
    asm volatile("cp.async.commit_group;" ::: "memory");
}
template<int N> __device__ __forceinline__ void cp_wait() {
    asm volatile("cp.async.wait_group %0;" :: "n"(N) : "memory");
}
__device__ __forceinline__ void mma_bf16(float* d, unsigned a0, unsigned a1,
                                         unsigned a2, unsigned a3,
                                         unsigned b0, unsigned b1) {
    asm volatile(
        "mma.sync.aligned.m16n8k16.row.col.f32.bf16.bf16.f32 "
        "{%0,%1,%2,%3}, {%4,%5,%6,%7}, {%8,%9}, {%0,%1,%2,%3};"
        : "+f"(d[0]), "+f"(d[1]), "+f"(d[2]), "+f"(d[3])
        : "r"(a0), "r"(a1), "r"(a2), "r"(a3), "r"(b0), "r"(b1));
}
__device__ __forceinline__ void mma_f16(float* d, unsigned a0, unsigned a1,
                                        unsigned a2, unsigned a3,
                                        unsigned b0, unsigned b1) {
    asm volatile(
        "mma.sync.aligned.m16n8k16.row.col.f32.f16.f16.f32 "
        "{%0,%1,%2,%3}, {%4,%5,%6,%7}, {%8,%9}, {%0,%1,%2,%3};"
        : "+f"(d[0]), "+f"(d[1]), "+f"(d[2]), "+f"(d[3])
        : "r"(a0), "r"(a1), "r"(a2), "r"(a3), "r"(b0), "r"(b1));
}

// =====================================================================
// K0: split x and W into bf16 hi/lo.
// blocks [0, 16384): x (1024 floats each). [16384, 16576): W.
// =====================================================================
__global__ __launch_bounds__(256) void split_kernel(
    const float* __restrict__ x,
    const float* __restrict__ Wk,
    const float* __restrict__ Wq,
    const float* __restrict__ Wv)
{
    const int bid = blockIdx.x;
    const int tid = threadIdx.x;

    const float* src;
    __nv_bfloat16 *dhi, *dlo;
    size_t off;
    if (bid < 16384) {
        src = x; off = (size_t)bid * 1024 + tid * 4;
        dhi = g_xhi; dlo = g_xlo;
    } else {
        int wb  = bid - 16384;           // 0..191
        int mat = wb >> 6;               // 64 blocks per mat
        src = (mat == 0) ? Wk : (mat == 1) ? Wq : Wv;
        off = (size_t)(wb & 63) * 1024 + tid * 4;
        dhi = g_whi + (size_t)mat * HS * D;
        dlo = g_wlo + (size_t)mat * HS * D;
    }

    float4 v = *(const float4*)(src + off);
    float vv[4] = {v.x, v.y, v.z, v.w};
    __nv_bfloat16 hi[4], lo[4];
#pragma unroll
    for (int j = 0; j < 4; j++) {
        hi[j] = __float2bfloat16(vv[j]);
        lo[j] = __float2bfloat16(vv[j] - __bfloat162float(hi[j]));
    }
    *(__nv_bfloat162*)(dhi + off)     = __halves2bfloat162(hi[0], hi[1]);
    *(__nv_bfloat162*)(dhi + off + 2) = __halves2bfloat162(hi[2], hi[3]);
    *(__nv_bfloat162*)(dlo + off)     = __halves2bfloat162(lo[0], lo[1]);
    *(__nv_bfloat162*)(dlo + off + 2) = __halves2bfloat162(lo[2], lo[3]);
}

// =====================================================================
// K1: proj GEMM via split-bf16 mma.sync. [16384 x 1024] . [1024 x 192].
// 128 blocks (128 rows each), 256 threads = 8 warps (2m x 4n).
// Warp tile 64r x 48c. K-chunks of 64, cp.async double-buffered.
// =====================================================================
#define PJP 72
#define PJ_A_BYTES (128 * PJP * 2)       // 18432 per matrix
#define PJ_B_BYTES (192 * PJP * 2)       // 27648 per matrix
#define PJ_BUF_BYTES (2 * PJ_A_BYTES + 2 * PJ_B_BYTES)   // 92160
__global__ __launch_bounds__(256) void proj_mma_kernel(
    const float* __restrict__ bk,
    const float* __restrict__ bq,
    const float* __restrict__ bv)
{
    extern __shared__ __align__(16) unsigned char sm[];

    const int tid = threadIdx.x;
    const int m0  = blockIdx.x * 128;
    const int wid = tid >> 5, lane = tid & 31;
    const int wm  = wid >> 2, wn = wid & 3;
    const int g   = lane >> 2, tig = lane & 3;

    const float* bias[3] = {bk, bq, bv};

    auto Ahi = [&](int buf) { return (__nv_bfloat16*)(sm + buf * PJ_BUF_BYTES); };
    auto Alo = [&](int buf) { return (__nv_bfloat16*)(sm + buf * PJ_BUF_BYTES + PJ_A_BYTES); };
    auto Bhi = [&](int buf) { return (__nv_bfloat16*)(sm + buf * PJ_BUF_BYTES + 2 * PJ_A_BYTES); };
    auto Blo = [&](int buf) { return (__nv_bfloat16*)(sm + buf * PJ_BUF_BYTES + 2 * PJ_A_BYTES + PJ_B_BYTES); };

    auto stage = [&](int buf, int k0) {
        // A: 128 rows x 8 x 16B  (1024 cp / 256 thr = 4 each, x2 matrices)
#pragma unroll
        for (int i = 0; i < 4; i++) {
            int idx = tid + i * 256;
            int row = idx >> 3, c8 = idx & 7;
            size_t gsrc = (size_t)(m0 + row) * D + k0 + c8 * 8;
            int off = row * PJP + c8 * 8;
            cp_async16((char*)(Ahi(buf) + off), g_xhi + gsrc);
            cp_async16((char*)(Alo(buf) + off), g_xlo + gsrc);
        }
        // B: 192 rows x 8 x 16B  (1536 / 256 = 6 each, x2)
#pragma unroll
        for (int i = 0; i < 6; i++) {
            int idx = tid + i * 256;
            int row = idx >> 3, c8 = idx & 7;
            size_t gsrc = (size_t)row * D + k0 + c8 * 8;
            int off = row * PJP + c8 * 8;
            cp_async16((char*)(Bhi(buf) + off), g_whi + gsrc);
            cp_async16((char*)(Blo(buf) + off), g_wlo + gsrc);
        }
        cp_commit();
    };

    float acc[4][6][4];
#pragma unroll
    for (int mt = 0; mt < 4; mt++)
#pragma unroll
        for (int nt = 0; nt < 6; nt++)
#pragma unroll
            for (int e = 0; e < 4; e++) acc[mt][nt][e] = 0.f;

    stage(0, 0);

    const int NC = D / 64;   // 16
    for (int ck = 0; ck < NC; ck++) {
        const int buf = ck & 1;
        if (ck + 1 < NC) { stage(buf ^ 1, (ck + 1) * 64); cp_wait<1>(); }
        else             { cp_wait<0>(); }
        __syncthreads();

        const __nv_bfloat16* ah = Ahi(buf);
        const __nv_bfloat16* al = Alo(buf);
        const __nv_bfloat16* bh = Bhi(buf);
        const __nv_bfloat16* bl = Blo(buf);

#pragma unroll
        for (int ks = 0; ks < 4; ks++) {
            unsigned bfh[6][2], bfl[6][2];
#pragma unroll
            for (int nt = 0; nt < 6; nt++) {
                int nrow = wn * 48 + nt * 8 + g;
                const __nv_bfloat16* bp = bh + nrow * PJP + ks * 16 + tig * 2;
                bfh[nt][0] = *(const unsigned*)(bp);
                bfh[nt][1] = *(const unsigned*)(bp + 8);
                const __nv_bfloat16* bp2 = bl + nrow * PJP + ks * 16 + tig * 2;
                bfl[nt][0] = *(const unsigned*)(bp2);
                bfl[nt][1] = *(const unsigned*)(bp2 + 8);
            }
#pragma unroll
            for (int mt = 0; mt < 4; mt++) {
                int arow = wm * 64 + mt * 16 + g;
                const __nv_bfloat16* ap = ah + arow * PJP + ks * 16 + tig * 2;
                unsigned ah0 = *(const unsigned*)(ap);
                unsigned ah1 = *(const unsigned*)(ap + 8 * PJP);
                unsigned ah2 = *(const unsigned*)(ap + 8);
                unsigned ah3 = *(const unsigned*)(ap + 8 * PJP + 8);
                const __nv_bfloat16* ap2 = al + arow * PJP + ks * 16 + tig * 2;
                unsigned al0 = *(const unsigned*)(ap2);
                unsigned al1 = *(const unsigned*)(ap2 + 8 * PJP);
                unsigned al2 = *(const unsigned*)(ap2 + 8);
                unsigned al3 = *(const unsigned*)(ap2 + 8 * PJP + 8);
#pragma unroll
                for (int nt = 0; nt < 6; nt++) {
                    mma_bf16(acc[mt][nt], ah0, ah1, ah2, ah3, bfh[nt][0], bfh[nt][1]);
                    mma_bf16(acc[mt][nt], ah0, ah1, ah2, ah3, bfl[nt][0], bfl[nt][1]);
                    mma_bf16(acc[mt][nt], al0, al1, al2, al3, bfh[nt][0], bfh[nt][1]);
                }
            }
        }
        __syncthreads();
    }

    // ---- epilogue ----
#pragma unroll
    for (int mt = 0; mt < 4; mt++) {
#pragma unroll
        for (int nt = 0; nt < 6; nt++) {
            int col = wn * 48 + nt * 8 + tig * 2;
            int mat = col >> 6, h = col & 63;
            float b0 = bias[mat][h], b1 = bias[mat][h + 1];
#pragma unroll
            for (int half = 0; half < 2; half++) {
                int row = m0 + wm * 64 + mt * 16 + g + half * 8;
                float v0 = acc[mt][nt][half * 2 + 0] + b0;
                float v1 = acc[mt][nt][half * 2 + 1] + b1;
                int b = row >> 11, t = row & (T - 1);
                if (mat == 2) {
                    __half h0 = __float2half_rn(v0);
                    __half h1 = __float2half_rn(v1);
                    size_t a0 = (size_t)(b * HS + h) * T + t;
                    g_vthi[a0] = h0;
                    g_vtlo[a0] = __float2half_rn(v0 - __half2float(h0));
                    g_vthi[a0 + T] = h1;
                    g_vtlo[a0 + T] = __float2half_rn(v1 - __half2float(h1));
                } else {
                    __nv_bfloat16 h0 = __float2bfloat16(v0);
                    __nv_bfloat16 h1 = __float2bfloat16(v1);
                    __nv_bfloat16 l0 = __float2bfloat16(v0 - __bfloat162float(h0));
                    __nv_bfloat16 l1 = __float2bfloat16(v1 - __bfloat162float(h1));
                    size_t base = (size_t)row * HS + h;
                    if (mat == 0) {
                        *(__nv_bfloat162*)(g_khi + base) = __halves2bfloat162(h0, h1);
                        *(__nv_bfloat162*)(g_klo + base) = __halves2bfloat162(l0, l1);
                    } else {
                        *(__nv_bfloat162*)(g_qhi + base) = __halves2bfloat162(h0, h1);
                        *(__nv_bfloat162*)(g_qlo + base) = __halves2bfloat162(l0, l1);
                        size_t qa = (size_t)(b * HS + h) * T + t;
                        g_qT[qa] = v0;
                        g_qT[qa + T] = v1;
                    }
                }
            }
        }
    }
}

// =====================================================================
// K2a: S = 8 * q k^T via mma.sync bf16 split (unchanged)
// =====================================================================
#define QKP 72
__global__ __launch_bounds__(256) void qk_mma_kernel()
{
    extern __shared__ __align__(16) unsigned char sm[];
    __nv_bfloat16* Qh = (__nv_bfloat16*)sm;
    __nv_bfloat16* Ql = Qh + 128 * QKP;
    __nv_bfloat16* Kh = Ql + 128 * QKP;
    __nv_bfloat16* Kl = Kh + 128 * QKP;
    float* Sst = (float*)sm;

    const int tid = threadIdx.x;
    const int v0 = blockIdx.x * 128;
    const int t0 = blockIdx.y * 128;
    const int b  = blockIdx.z;

#pragma unroll
    for (int it = 0; it < 4; it++) {
        int idx = tid + it * 256;
        int row = idx >> 3, c8 = idx & 7;
        const char* qh = (const char*)(g_qhi + (size_t)(b * T + t0 + row) * HS);
        const char* ql = (const char*)(g_qlo + (size_t)(b * T + t0 + row) * HS);
        const char* kh = (const char*)(g_khi + (size_t)(b * T + v0 + row) * HS);
        const char* kl = (const char*)(g_klo + (size_t)(b * T + v0 + row) * HS);
        int off = row * (QKP * 2) + c8 * 16;
        cp_async16((char*)Qh + off, qh + c8 * 16);
        cp_async16((char*)Ql + off, ql + c8 * 16);
        cp_async16((char*)Kh + off, kh + c8 * 16);
        cp_async16((char*)Kl + off, kl + c8 * 16);
    }
    cp_commit();
    cp_wait<0>();
    __syncthreads();

    const int wid = tid >> 5, lane = tid & 31;
    const int wm = wid >> 1, wn = wid & 1;
    const int g = lane >> 2, tig = lane & 3;

    float c[2][8][4];
#pragma unroll
    for (int mt = 0; mt < 2; mt++)
#pragma unroll
        for (int nt = 0; nt < 8; nt++)
#pragma unroll
            for (int e = 0; e < 4; e++) c[mt][nt][e] = 0.f;

    const __nv_bfloat16* Ab[3] = {Qh, Qh, Ql};
    const __nv_bfloat16* Bb[3] = {Kh, Kl, Kh};

#pragma unroll
    for (int p = 0; p < 3; p++) {
        const __nv_bfloat16* A = Ab[p];
        const __nv_bfloat16* Bm = Bb[p];
#pragma unroll
        for (int ks = 0; ks < 4; ks++) {
            unsigned bf[8][2];
#pragma unroll
            for (int nt = 0; nt < 8; nt++) {
                int vrow = wn * 64 + nt * 8 + g;
                const __nv_bfloat16* bp = Bm + vrow * QKP + ks * 16 + tig * 2;
                bf[nt][0] = *(const unsigned*)(bp);
                bf[nt][1] = *(const unsigned*)(bp + 8);
            }
#pragma unroll
            for (int mt = 0; mt < 2; mt++) {
                int trow = wm * 32 + mt * 16 + g;
                const __nv_bfloat16* ap = A + trow * QKP + ks * 16 + tig * 2;
                unsigned a0 = *(const unsigned*)(ap);
                unsigned a1 = *(const unsigned*)(ap + 8 * QKP);
                unsigned a2 = *(const unsigned*)(ap + 8);
                unsigned a3 = *(const unsigned*)(ap + 8 * QKP + 8);
#pragma unroll
                for (int nt = 0; nt < 8; nt++)
                    mma_bf16(c[mt][nt], a0, a1, a2, a3, bf[nt][0], bf[nt][1]);
            }
        }
    }

    __syncthreads();

#pragma unroll
    for (int mt = 0; mt < 2; mt++) {
        int r = wm * 32 + mt * 16 + g;
#pragma unroll
        for (int nt = 0; nt < 8; nt++) {
            int col = wn * 64 + nt * 8 + tig * 2;
            *(float2*)&Sst[r * 132 + col] =
                make_float2(8.f * c[mt][nt][0], 8.f * c[mt][nt][1]);
            *(float2*)&Sst[(r + 8) * 132 + col] =
                make_float2(8.f * c[mt][nt][2], 8.f * c[mt][nt][3]);
        }
    }
    __syncthreads();

#pragma unroll
    for (int it = 0; it < 16; it++) {
        int idx = tid + it * 256;
        int row = idx >> 5, c4 = idx & 31;
        float4 val = *(const float4*)&Sst[row * 132 + c4 * 4];
        *(float4*)(g_s + ((size_t)(b * T + t0 + row)) * T + v0 + c4 * 4) = val;
    }
}

// =====================================================================
// K2b: S += q . rel (unchanged)
// =====================================================================
__global__ __launch_bounds__(256, 1) void rel_kernel(const float* __restrict__ rel)
{
    __shared__ float4 R4[2][256][16];
    __shared__ __align__(16) ull qsP[4][64];

    const int t   = blockIdx.x;
    const int tid = threadIdx.x;

    {
        int pr = tid >> 6;
        int c  = tid & 63;
        float qa = g_qT[(size_t)((2 * pr + 0) * HS + c) * T + t];
        float qb = g_qT[(size_t)((2 * pr + 1) * HS + c) * T + t];
        qsP[pr][c] = pack2(qa, qb);
    }

    const int v  = tid;
    const int sw = tid & 15;

    const float4* relt = (const float4*)(rel + (size_t)t * T * HS);
    const size_t TT = (size_t)T * T;
    const size_t srow0 = (size_t)t * T;

    const int lvv = tid >> 4;
    const int lc4 = tid & 15;

#pragma unroll
    for (int it = 0; it < 16; it++) {
        int vv = lvv + it * 16;
        cp_async16(&R4[0][vv][lc4 ^ (vv & 15)], &relt[(size_t)vv * 16 + lc4]);
    }
    cp_commit();

    const int NT = T / 256;
    for (int n = 0; n < NT; n++) {
        int buf = n & 1;
        if (n + 1 < NT) {
#pragma unroll
            for (int it = 0; it < 16; it++) {
                int vv = lvv + it * 16;
                cp_async16(&R4[buf ^ 1][vv][lc4 ^ (vv & 15)],
                           &relt[(size_t)((n + 1) * 256 + vv) * 16 + lc4]);
            }
            cp_commit();
            cp_wait<1>();
        } else {
            cp_wait<0>();
        }
        __syncthreads();

        size_t si = srow0 + n * 256 + v;
        float s[8];
#pragma unroll
        for (int bb = 0; bb < 8; bb++) s[bb] = g_s[si + (size_t)bb * TT];

        ull acc[4] = {0ull, 0ull, 0ull, 0ull};
#pragma unroll
        for (int c4 = 0; c4 < 16; c4++) {
            float4 r4 = R4[buf][v][c4 ^ sw];
            ull rx = splat2(r4.x), ry = splat2(r4.y), rz = splat2(r4.z), rw = splat2(r4.w);
#pragma unroll
            for (int pr = 0; pr < 4; pr++) {
                ulonglong2 qa = *(const ulonglong2*)&qsP[pr][c4 * 4];
                ulonglong2 qb = *(const ulonglong2*)&qsP[pr][c4 * 4 + 2];
                ffma2(acc[pr], qa.x, rx);
                ffma2(acc[pr], qa.y, ry);
                ffma2(acc[pr], qb.x, rz);
                ffma2(acc[pr], qb.y, rw);
            }
        }

#pragma unroll
        for (int pr = 0; pr < 4; pr++) {
            float2 f = unpack2(acc[pr]);
            g_s[si + (size_t)(2 * pr + 0) * TT] = s[2 * pr + 0] + f.x;
            g_s[si + (size_t)(2 * pr + 1) * TT] = s[2 * pr + 1] + f.y;
        }
        __syncthreads();
    }
}

// =====================================================================
// K3: softmax + PV via fp16 HMMA (unchanged)
// =====================================================================
#define ATP 2056
#define VTP 72
__global__ __launch_bounds__(512, 2) void soft_pv_kernel(float* __restrict__ out)
{
    extern __shared__ __align__(16) unsigned char smraw[];
    __half* attH = (__half*)smraw;
    __half* Vts  = (__half*)(smraw + 65792);
    float*  pout = (float*)(smraw + 65792 + 36864);
    __shared__ float invl[16];

    const int t0   = blockIdx.x * 16;
    const int b    = blockIdx.y;
    const int tid  = threadIdx.x;
    const int w    = tid >> 5;
    const int lane = tid & 31;
    const int g    = lane >> 2;
    const int tig  = lane & 3;

    {
        const float4* srow4 = (const float4*)(g_s + ((size_t)(b * T + t0 + w)) * T);
        float m = -3.4e38f;
#pragma unroll
        for (int i = 0; i < 16; i++) {
            float4 sv = srow4[i * 32 + lane];
            m = fmaxf(m, fmaxf(fmaxf(sv.x, sv.y), fmaxf(sv.z, sv.w)));
        }
#pragma unroll
        for (int o = 16; o > 0; o >>= 1)
            m = fmaxf(m, __shfl_xor_sync(0xffffffffu, m, o));

        const float* srow = g_s + ((size_t)(b * T + t0 + w)) * T;
        float sum = 0.f;
#pragma unroll 8
        for (int i = 0; i < 64; i++) {
            int vi = i * 32 + lane;
            float e = __expf(srow[vi] - m);
            attH[w * ATP + vi] = __float2half_rn(e);
            sum += e;
        }
#pragma unroll
        for (int o = 16; o > 0; o >>= 1)
            sum += __shfl_xor_sync(0xffffffffu, sum, o);
        if (lane == 0) invl[w] = 1.f / sum;
    }

    const int hf = w & 1;
    const int ht = w >> 1;
    float d[4] = {0.f, 0.f, 0.f, 0.f};

    const int sel   = tid >> 8;
    const int hh    = (tid & 255) >> 2;
    const int cpair = tid & 3;
    const __half* vsrc = (sel ? g_vtlo : g_vthi) + (size_t)(b * HS + hh) * T;

#pragma unroll
    for (int u = 0; u < 2; u++) {
        int c16 = cpair * 2 + u;
        cp_async16(&Vts[((0 * 2 + sel) * 64 + hh) * VTP + c16 * 8], vsrc + c16 * 8);
    }
    cp_commit();

    const int NT = T / 64;
    for (int ck = 0; ck < NT; ck++) {
        const int buf = ck & 1;
        cp_wait<0>();
        __syncthreads();

        if (ck + 1 < NT) {
            const __half* src2 = vsrc + (ck + 1) * 64;
#pragma unroll
            for (int u = 0; u < 2; u++) {
                int c16 = cpair * 2 + u;
                cp_async16(&Vts[(((buf ^ 1) * 2 + sel) * 64 + hh) * VTP + c16 * 8],
                           src2 + c16 * 8);
            }
            cp_commit();
        }

        const int v0 = ck * 64;
#pragma unroll
        for (int ks = 0; ks < 2; ks++) {
            int vloc = hf * 32 + ks * 16;
            const __half* ap = attH + g * ATP + v0 + vloc + 2 * tig;
            unsigned a0 = *(const unsigned*)(ap);
            unsigned a1 = *(const unsigned*)(ap + 8 * ATP);
            unsigned a2 = *(const unsigned*)(ap + 8);
            unsigned a3 = *(const unsigned*)(ap + 8 * ATP + 8);
            const __half* bh = &Vts[((buf * 2 + 0) * 64 + ht * 8 + g) * VTP + vloc + 2 * tig];
            mma_f16(d, a0, a1, a2, a3,
                    *(const unsigned*)bh, *(const unsigned*)(bh + 8));
            const __half* bl = &Vts[((buf * 2 + 1) * 64 + ht * 8 + g) * VTP + vloc + 2 * tig];
            mma_f16(d, a0, a1, a2, a3,
                    *(const unsigned*)bl, *(const unsigned*)(bl + 8));
        }
    }

    {
        float* pw = pout + w * 128;
        *(float2*)&pw[g * 8 + 2 * tig]       = make_float2(d[0], d[1]);
        *(float2*)&pw[(g + 8) * 8 + 2 * tig] = make_float2(d[2], d[3]);
    }
    __syncthreads();

    {
        int t   = tid >> 5;
        int hl  = tid & 31;
        int ht2 = hl >> 2;
        int hloc = (hl & 3) * 2;
        float2 p0 = *(const float2*)&pout[(ht2 * 2 + 0) * 128 + t * 8 + hloc];
        float2 p1 = *(const float2*)&pout[(ht2 * 2 + 1) * 128 + t * 8 + hloc];
        float sc = invl[t];
        *(float2*)(out + ((size_t)(b * T + t0 + t)) * HS + hl * 2) =
            make_float2((p0.x + p1.x) * sc, (p0.y + p1.y) * sc);
    }
}

// =====================================================================
extern "C" void kernel_launch(void* const* d_in, const int* in_sizes, int n_in,
                              void* d_out, int out_size)
{
    (void)in_sizes; (void)n_in; (void)out_size;
    const float* x   = (const float*)d_in[0];
    const float* Wk  = (const float*)d_in[1];
    const float* bk  = (const float*)d_in[2];
    const float* Wq  = (const float*)d_in[3];
    const float* bq  = (const float*)d_in[4];
    const float* Wv  = (const float*)d_in[5];
    const float* bv  = (const float*)d_in[6];
    const float* rel = (const float*)d_in[7];
    float* out = (float*)d_out;

    split_kernel<<<16384 + 192, 256>>>(x, Wk, Wq, Wv);

    const int pj_smem = 2 * PJ_BUF_BYTES;   // 184320
    cudaFuncSetAttribute(proj_mma_kernel, cudaFuncAttributeMaxDynamicSharedMemorySize, pj_smem);
    proj_mma_kernel<<<128, 256, pj_smem>>>(bk, bq, bv);

    const int qk_smem = 4 * 128 * QKP * (int)sizeof(__nv_bfloat16);
    cudaFuncSetAttribute(qk_mma_kernel, cudaFuncAttributeMaxDynamicSharedMemorySize, qk_smem);
    qk_mma_kernel<<<dim3(T / 128, T / 128, B), 256, qk_smem>>>();

    rel_kernel<<<T, 256>>>(rel);

    const int k3_smem = 65792 + 36864 + 8192;
    cudaFuncSetAttribute(soft_pv_kernel, cudaFuncAttributeMaxDynamicSharedMemorySize, k3_smem);
    soft_pv_kernel<<<dim3(T / 16, B), 512, k3_smem>>>(out);
}

// round 15
// speedup vs baseline: 1.7162x; 1.0148x over previous
#include <cuda_runtime.h>
#include <cuda_fp16.h>
#include <cuda_bf16.h>

#define B 8
#define T 2048
#define D 1024
#define HS 64

typedef unsigned long long ull;

// ---- device scratch ----
__device__ float g_qT[B * HS * T];                               // [b][c][t] (rel)
__device__ float g_s [(size_t)B * T * T];                        // [b][t][v]
__device__ __align__(16) __nv_bfloat16 g_qhi[B * T * HS];        // [b][t][c]
__device__ __align__(16) __nv_bfloat16 g_qlo[B * T * HS];
__device__ __align__(16) __nv_bfloat16 g_khi[B * T * HS];
__device__ __align__(16) __nv_bfloat16 g_klo[B * T * HS];
__device__ __align__(16) __half g_vthi[B * HS * T];              // [b][h][t]
__device__ __align__(16) __half g_vtlo[B * HS * T];
__device__ __align__(16) __nv_bfloat16 g_xhi[B * T * D];         // [row][c]
__device__ __align__(16) __nv_bfloat16 g_xlo[B * T * D];
__device__ __align__(16) __nv_bfloat16 g_whi[3 * HS * D];        // [mat*64+h][c]
__device__ __align__(16) __nv_bfloat16 g_wlo[3 * HS * D];

// ---- packed f32x2 helpers ----
__device__ __forceinline__ ull splat2(float a) {
    ull r; asm("mov.b64 %0, {%1, %1};" : "=l"(r) : "f"(a)); return r;
}
__device__ __forceinline__ ull pack2(float x, float y) {
    ull r; asm("mov.b64 %0, {%1, %2};" : "=l"(r) : "f"(x), "f"(y)); return r;
}
__device__ __forceinline__ void ffma2(ull& d, ull a, ull b) {
    asm("fma.rn.f32x2 %0, %1, %2, %0;" : "+l"(d) : "l"(a), "l"(b));
}
__device__ __forceinline__ float2 unpack2(ull v) {
    float2 f; asm("mov.b64 {%0, %1}, %2;" : "=f"(f.x), "=f"(f.y) : "l"(v)); return f;
}
__device__ __forceinline__ void cp_async16(void* smem_dst, const void* gmem_src) {
    unsigned sa = (unsigned)__cvta_generic_to_shared(smem_dst);
    asm volatile("cp.async.cg.shared.global [%0], [%1], 16;" :: "r"(sa), "l"(gmem_src) : "memory");
}
__device__ __forceinline__ void cp_commit() {
    asm volatile("cp.async.commit_group;" ::: "memory");
}
template<int N> __device__ __forceinline__ void cp_wait() {
    asm volatile("cp.async.wait_group %0;" :: "n"(N) : "memory");
}
__device__ __forceinline__ void mma_bf16(float* d, unsigned a0, unsigned a1,
                                         unsigned a2, unsigned a3,
                                         unsigned b0, unsigned b1) {
    asm volatile(
        "mma.sync.aligned.m16n8k16.row.col.f32.bf16.bf16.f32 "
        "{%0,%1,%2,%3}, {%4,%5,%6,%7}, {%8,%9}, {%0,%1,%2,%3};"
        : "+f"(d[0]), "+f"(d[1]), "+f"(d[2]), "+f"(d[3])
        : "r"(a0), "r"(a1), "r"(a2), "r"(a3), "r"(b0), "r"(b1));
}
__device__ __forceinline__ void mma_f16(float* d, unsigned a0, unsigned a1,
                                        unsigned a2, unsigned a3,
                                        unsigned b0, unsigned b1) {
    asm volatile(
        "mma.sync.aligned.m16n8k16.row.col.f32.f16.f16.f32 "
        "{%0,%1,%2,%3}, {%4,%5,%6,%7}, {%8,%9}, {%0,%1,%2,%3};"
        : "+f"(d[0]), "+f"(d[1]), "+f"(d[2]), "+f"(d[3])
        : "r"(a0), "r"(a1), "r"(a2), "r"(a3), "r"(b0), "r"(b1));
}

// =====================================================================
// K0: split x and W into bf16 hi/lo (unchanged)
// =====================================================================
__global__ __launch_bounds__(256) void split_kernel(
    const float* __restrict__ x,
    const float* __restrict__ Wk,
    const float* __restrict__ Wq,
    const float* __restrict__ Wv)
{
    const int bid = blockIdx.x;
    const int tid = threadIdx.x;

    const float* src;
    __nv_bfloat16 *dhi, *dlo;
    size_t off;
    if (bid < 16384) {
        src = x; off = (size_t)bid * 1024 + tid * 4;
        dhi = g_xhi; dlo = g_xlo;
    } else {
        int wb  = bid - 16384;
        int mat = wb >> 6;
        src = (mat == 0) ? Wk : (mat == 1) ? Wq : Wv;
        off = (size_t)(wb & 63) * 1024 + tid * 4;
        dhi = g_whi + (size_t)mat * HS * D;
        dlo = g_wlo + (size_t)mat * HS * D;
    }

    float4 v = *(const float4*)(src + off);
    float vv[4] = {v.x, v.y, v.z, v.w};
    __nv_bfloat16 hi[4], lo[4];
#pragma unroll
    for (int j = 0; j < 4; j++) {
        hi[j] = __float2bfloat16(vv[j]);
        lo[j] = __float2bfloat16(vv[j] - __bfloat162float(hi[j]));
    }
    *(__nv_bfloat162*)(dhi + off)     = __halves2bfloat162(hi[0], hi[1]);
    *(__nv_bfloat162*)(dhi + off + 2) = __halves2bfloat162(hi[2], hi[3]);
    *(__nv_bfloat162*)(dlo + off)     = __halves2bfloat162(lo[0], lo[1]);
    *(__nv_bfloat162*)(dlo + off + 2) = __halves2bfloat162(lo[2], lo[3]);
}

// =====================================================================
// K1: proj GEMM via split-bf16 mma.sync (unchanged from R13)
// =====================================================================
#define PJP 72
#define PJ_A_BYTES (128 * PJP * 2)
#define PJ_B_BYTES (192 * PJP * 2)
#define PJ_BUF_BYTES (2 * PJ_A_BYTES + 2 * PJ_B_BYTES)
__global__ __launch_bounds__(256) void proj_mma_kernel(
    const float* __restrict__ bk,
    const float* __restrict__ bq,
    const float* __restrict__ bv)
{
    extern __shared__ __align__(16) unsigned char sm[];

    const int tid = threadIdx.x;
    const int m0  = blockIdx.x * 128;
    const int wid = tid >> 5, lane = tid & 31;
    const int wm  = wid >> 2, wn = wid & 3;
    const int g   = lane >> 2, tig = lane & 3;

    const float* bias[3] = {bk, bq, bv};

    auto Ahi = [&](int buf) { return (__nv_bfloat16*)(sm + buf * PJ_BUF_BYTES); };
    auto Alo = [&](int buf) { return (__nv_bfloat16*)(sm + buf * PJ_BUF_BYTES + PJ_A_BYTES); };
    auto Bhi = [&](int buf) { return (__nv_bfloat16*)(sm + buf * PJ_BUF_BYTES + 2 * PJ_A_BYTES); };
    auto Blo = [&](int buf) { return (__nv_bfloat16*)(sm + buf * PJ_BUF_BYTES + 2 * PJ_A_BYTES + PJ_B_BYTES); };

    auto stage = [&](int buf, int k0) {
#pragma unroll
        for (int i = 0; i < 4; i++) {
            int idx = tid + i * 256;
            int row = idx >> 3, c8 = idx & 7;
            size_t gsrc = (size_t)(m0 + row) * D + k0 + c8 * 8;
            int off = row * PJP + c8 * 8;
            cp_async16((char*)(Ahi(buf) + off), g_xhi + gsrc);
            cp_async16((char*)(Alo(buf) + off), g_xlo + gsrc);
        }
#pragma unroll
        for (int i = 0; i < 6; i++) {
            int idx = tid + i * 256;
            int row = idx >> 3, c8 = idx & 7;
            size_t gsrc = (size_t)row * D + k0 + c8 * 8;
            int off = row * PJP + c8 * 8;
            cp_async16((char*)(Bhi(buf) + off), g_whi + gsrc);
            cp_async16((char*)(Blo(buf) + off), g_wlo + gsrc);
        }
        cp_commit();
    };

    float acc[4][6][4];
#pragma unroll
    for (int mt = 0; mt < 4; mt++)
#pragma unroll
        for (int nt = 0; nt < 6; nt++)
#pragma unroll
            for (int e = 0; e < 4; e++) acc[mt][nt][e] = 0.f;

    stage(0, 0);

    const int NC = D / 64;
    for (int ck = 0; ck < NC; ck++) {
        const int buf = ck & 1;
        if (ck + 1 < NC) { stage(buf ^ 1, (ck + 1) * 64); cp_wait<1>(); }
        else             { cp_wait<0>(); }
        __syncthreads();

        const __nv_bfloat16* ah = Ahi(buf);
        const __nv_bfloat16* al = Alo(buf);
        const __nv_bfloat16* bh = Bhi(buf);
        const __nv_bfloat16* bl = Blo(buf);

#pragma unroll
        for (int ks = 0; ks < 4; ks++) {
            unsigned bfh[6][2], bfl[6][2];
#pragma unroll
            for (int nt = 0; nt < 6; nt++) {
                int nrow = wn * 48 + nt * 8 + g;
                const __nv_bfloat16* bp = bh + nrow * PJP + ks * 16 + tig * 2;
                bfh[nt][0] = *(const unsigned*)(bp);
                bfh[nt][1] = *(const unsigned*)(bp + 8);
                const __nv_bfloat16* bp2 = bl + nrow * PJP + ks * 16 + tig * 2;
                bfl[nt][0] = *(const unsigned*)(bp2);
                bfl[nt][1] = *(const unsigned*)(bp2 + 8);
            }
#pragma unroll
            for (int mt = 0; mt < 4; mt++) {
                int arow = wm * 64 + mt * 16 + g;
                const __nv_bfloat16* ap = ah + arow * PJP + ks * 16 + tig * 2;
                unsigned ah0 = *(const unsigned*)(ap);
                unsigned ah1 = *(const unsigned*)(ap + 8 * PJP);
                unsigned ah2 = *(const unsigned*)(ap + 8);
                unsigned ah3 = *(const unsigned*)(ap + 8 * PJP + 8);
                const __nv_bfloat16* ap2 = al + arow * PJP + ks * 16 + tig * 2;
                unsigned al0 = *(const unsigned*)(ap2);
                unsigned al1 = *(const unsigned*)(ap2 + 8 * PJP);
                unsigned al2 = *(const unsigned*)(ap2 + 8);
                unsigned al3 = *(const unsigned*)(ap2 + 8 * PJP + 8);
#pragma unroll
                for (int nt = 0; nt < 6; nt++) {
                    mma_bf16(acc[mt][nt], ah0, ah1, ah2, ah3, bfh[nt][0], bfh[nt][1]);
                    mma_bf16(acc[mt][nt], ah0, ah1, ah2, ah3, bfl[nt][0], bfl[nt][1]);
                    mma_bf16(acc[mt][nt], al0, al1, al2, al3, bfh[nt][0], bfh[nt][1]);
                }
            }
        }
        __syncthreads();
    }

#pragma unroll
    for (int mt = 0; mt < 4; mt++) {
#pragma unroll
        for (int nt = 0; nt < 6; nt++) {
            int col = wn * 48 + nt * 8 + tig * 2;
            int mat = col >> 6, h = col & 63;
            float b0 = bias[mat][h], b1 = bias[mat][h + 1];
#pragma unroll
            for (int half = 0; half < 2; half++) {
                int row = m0 + wm * 64 + mt * 16 + g + half * 8;
                float v0 = acc[mt][nt][half * 2 + 0] + b0;
                float v1 = acc[mt][nt][half * 2 + 1] + b1;
                int b = row >> 11, t = row & (T - 1);
                if (mat == 2) {
                    __half h0 = __float2half_rn(v0);
                    __half h1 = __float2half_rn(v1);
                    size_t a0 = (size_t)(b * HS + h) * T + t;
                    g_vthi[a0] = h0;
                    g_vtlo[a0] = __float2half_rn(v0 - __half2float(h0));
                    g_vthi[a0 + T] = h1;
                    g_vtlo[a0 + T] = __float2half_rn(v1 - __half2float(h1));
                } else {
                    __nv_bfloat16 h0 = __float2bfloat16(v0);
                    __nv_bfloat16 h1 = __float2bfloat16(v1);
                    __nv_bfloat16 l0 = __float2bfloat16(v0 - __bfloat162float(h0));
                    __nv_bfloat16 l1 = __float2bfloat16(v1 - __bfloat162float(h1));
                    size_t base = (size_t)row * HS + h;
                    if (mat == 0) {
                        *(__nv_bfloat162*)(g_khi + base) = __halves2bfloat162(h0, h1);
                        *(__nv_bfloat162*)(g_klo + base) = __halves2bfloat162(l0, l1);
                    } else {
                        *(__nv_bfloat162*)(g_qhi + base) = __halves2bfloat162(h0, h1);
                        *(__nv_bfloat162*)(g_qlo + base) = __halves2bfloat162(l0, l1);
                        size_t qa = (size_t)(b * HS + h) * T + t;
                        g_qT[qa] = v0;
                        g_qT[qa + T] = v1;
                    }
                }
            }
        }
    }
}

// =====================================================================
// K2a: S = 8 * q k^T via mma.sync bf16 split (unchanged)
// =====================================================================
#define QKP 72
__global__ __launch_bounds__(256) void qk_mma_kernel()
{
    extern __shared__ __align__(16) unsigned char sm[];
    __nv_bfloat16* Qh = (__nv_bfloat16*)sm;
    __nv_bfloat16* Ql = Qh + 128 * QKP;
    __nv_bfloat16* Kh = Ql + 128 * QKP;
    __nv_bfloat16* Kl = Kh + 128 * QKP;
    float* Sst = (float*)sm;

    const int tid = threadIdx.x;
    const int v0 = blockIdx.x * 128;
    const int t0 = blockIdx.y * 128;
    const int b  = blockIdx.z;

#pragma unroll
    for (int it = 0; it < 4; it++) {
        int idx = tid + it * 256;
        int row = idx >> 3, c8 = idx & 7;
        const char* qh = (const char*)(g_qhi + (size_t)(b * T + t0 + row) * HS);
        const char* ql = (const char*)(g_qlo + (size_t)(b * T + t0 + row) * HS);
        const char* kh = (const char*)(g_khi + (size_t)(b * T + v0 + row) * HS);
        const char* kl = (const char*)(g_klo + (size_t)(b * T + v0 + row) * HS);
        int off = row * (QKP * 2) + c8 * 16;
        cp_async16((char*)Qh + off, qh + c8 * 16);
        cp_async16((char*)Ql + off, ql + c8 * 16);
        cp_async16((char*)Kh + off, kh + c8 * 16);
        cp_async16((char*)Kl + off, kl + c8 * 16);
    }
    cp_commit();
    cp_wait<0>();
    __syncthreads();

    const int wid = tid >> 5, lane = tid & 31;
    const int wm = wid >> 1, wn = wid & 1;
    const int g = lane >> 2, tig = lane & 3;

    float c[2][8][4];
#pragma unroll
    for (int mt = 0; mt < 2; mt++)
#pragma unroll
        for (int nt = 0; nt < 8; nt++)
#pragma unroll
            for (int e = 0; e < 4; e++) c[mt][nt][e] = 0.f;

    const __nv_bfloat16* Ab[3] = {Qh, Qh, Ql};
    const __nv_bfloat16* Bb[3] = {Kh, Kl, Kh};

#pragma unroll
    for (int p = 0; p < 3; p++) {
        const __nv_bfloat16* A = Ab[p];
        const __nv_bfloat16* Bm = Bb[p];
#pragma unroll
        for (int ks = 0; ks < 4; ks++) {
            unsigned bf[8][2];
#pragma unroll
            for (int nt = 0; nt < 8; nt++) {
                int vrow = wn * 64 + nt * 8 + g;
                const __nv_bfloat16* bp = Bm + vrow * QKP + ks * 16 + tig * 2;
                bf[nt][0] = *(const unsigned*)(bp);
                bf[nt][1] = *(const unsigned*)(bp + 8);
            }
#pragma unroll
            for (int mt = 0; mt < 2; mt++) {
                int trow = wm * 32 + mt * 16 + g;
                const __nv_bfloat16* ap = A + trow * QKP + ks * 16 + tig * 2;
                unsigned a0 = *(const unsigned*)(ap);
                unsigned a1 = *(const unsigned*)(ap + 8 * QKP);
                unsigned a2 = *(const unsigned*)(ap + 8);
                unsigned a3 = *(const unsigned*)(ap + 8 * QKP + 8);
#pragma unroll
                for (int nt = 0; nt < 8; nt++)
                    mma_bf16(c[mt][nt], a0, a1, a2, a3, bf[nt][0], bf[nt][1]);
            }
        }
    }

    __syncthreads();

#pragma unroll
    for (int mt = 0; mt < 2; mt++) {
        int r = wm * 32 + mt * 16 + g;
#pragma unroll
        for (int nt = 0; nt < 8; nt++) {
            int col = wn * 64 + nt * 8 + tig * 2;
            *(float2*)&Sst[r * 132 + col] =
                make_float2(8.f * c[mt][nt][0], 8.f * c[mt][nt][1]);
            *(float2*)&Sst[(r + 8) * 132 + col] =
                make_float2(8.f * c[mt][nt][2], 8.f * c[mt][nt][3]);
        }
    }
    __syncthreads();

#pragma unroll
    for (int it = 0; it < 16; it++) {
        int idx = tid + it * 256;
        int row = idx >> 5, c4 = idx & 31;
        float4 val = *(const float4*)&Sst[row * 132 + c4 * 4];
        *(float4*)(g_s + ((size_t)(b * T + t0 + row)) * T + v0 + c4 * 4) = val;
    }
}

// =====================================================================
// K2b: S += q . rel.  Tile 128 v double-buffered (64KB) -> 2 CTAs/SM.
// 256 threads: v = tid&127, pg = tid>>7 (2 b-pairs each).
// =====================================================================
__global__ __launch_bounds__(256, 2) void rel_kernel(const float* __restrict__ rel)
{
    __shared__ float4 R4[2][128][16];                 // 64 KB
    __shared__ __align__(16) ull qsP[4][64];          // 2 KB

    const int t   = blockIdx.x;
    const int tid = threadIdx.x;

    // stage q pairs: thread (pr = tid>>6, c = tid&63)
    {
        int pr = tid >> 6;
        int c  = tid & 63;
        float qa = g_qT[(size_t)((2 * pr + 0) * HS + c) * T + t];
        float qb = g_qT[(size_t)((2 * pr + 1) * HS + c) * T + t];
        qsP[pr][c] = pack2(qa, qb);
    }

    const int v  = tid & 127;
    const int pg = tid >> 7;          // 0/1 -> pairs 2pg, 2pg+1 (batches 4pg..4pg+3)
    const int sw = v & 15;

    const float4* relt = (const float4*)(rel + (size_t)t * T * HS);
    const size_t TT = (size_t)T * T;
    const size_t srow0 = ((size_t)(4 * pg) * T + t) * T;

    const int lvv = tid >> 4;        // 0..15 (+16 per it, 8 its)
    const int lc4 = tid & 15;

    // prefetch tile 0
#pragma unroll
    for (int it = 0; it < 8; it++) {
        int vv = lvv + it * 16;
        cp_async16(&R4[0][vv][lc4 ^ (vv & 15)], &relt[(size_t)vv * 16 + lc4]);
    }
    cp_commit();

    const int NT = T / 128;   // 16 tiles
    for (int n = 0; n < NT; n++) {
        int buf = n & 1;
        if (n + 1 < NT) {
#pragma unroll
            for (int it = 0; it < 8; it++) {
                int vv = lvv + it * 16;
                cp_async16(&R4[buf ^ 1][vv][lc4 ^ (vv & 15)],
                           &relt[(size_t)((n + 1) * 128 + vv) * 16 + lc4]);
            }
            cp_commit();
            cp_wait<1>();
        } else {
            cp_wait<0>();
        }
        __syncthreads();

        size_t si = srow0 + n * 128 + v;
        float s0 = g_s[si], s1 = g_s[si + TT];
        float s2 = g_s[si + 2 * TT], s3 = g_s[si + 3 * TT];

        ull acc0 = 0ull, acc1 = 0ull;
        const ull* qp0 = qsP[2 * pg + 0];
        const ull* qp1 = qsP[2 * pg + 1];
#pragma unroll
        for (int c4 = 0; c4 < 16; c4++) {
            float4 r4 = R4[buf][v][c4 ^ sw];
            ulonglong2 qa0 = *(const ulonglong2*)&qp0[c4 * 4];
            ulonglong2 qb0 = *(const ulonglong2*)&qp0[c4 * 4 + 2];
            ulonglong2 qa1 = *(const ulonglong2*)&qp1[c4 * 4];
            ulonglong2 qb1 = *(const ulonglong2*)&qp1[c4 * 4 + 2];
            ull rx = splat2(r4.x), ry = splat2(r4.y);
            ull rz = splat2(r4.z), rw = splat2(r4.w);
            ffma2(acc0, qa0.x, rx); ffma2(acc1, qa1.x, rx);
            ffma2(acc0, qa0.y, ry); ffma2(acc1, qa1.y, ry);
            ffma2(acc0, qb0.x, rz); ffma2(acc1, qb1.x, rz);
            ffma2(acc0, qb0.y, rw); ffma2(acc1, qb1.y, rw);
        }

        float2 f0 = unpack2(acc0), f1 = unpack2(acc1);
        g_s[si]          = s0 + f0.x;
        g_s[si + TT]     = s1 + f0.y;
        g_s[si + 2 * TT] = s2 + f1.x;
        g_s[si + 3 * TT] = s3 + f1.y;

        __syncthreads();
    }
}

// =====================================================================
// K3: softmax + PV via fp16 HMMA (unchanged)
// =====================================================================
#define ATP 2056
#define VTP 72
__global__ __launch_bounds__(512, 2) void soft_pv_kernel(float* __restrict__ out)
{
    extern __shared__ __align__(16) unsigned char smraw[];
    __half* attH = (__half*)smraw;
    __half* Vts  = (__half*)(smraw + 65792);
    float*  pout = (float*)(smraw + 65792 + 36864);
    __shared__ float invl[16];

    const int t0   = blockIdx.x * 16;
    const int b    = blockIdx.y;
    const int tid  = threadIdx.x;
    const int w    = tid >> 5;
    const int lane = tid & 31;
    const int g    = lane >> 2;
    const int tig  = lane & 3;

    {
        const float4* srow4 = (const float4*)(g_s + ((size_t)(b * T + t0 + w)) * T);
        float m = -3.4e38f;
#pragma unroll
        for (int i = 0; i < 16; i++) {
            float4 sv = srow4[i * 32 + lane];
            m = fmaxf(m, fmaxf(fmaxf(sv.x, sv.y), fmaxf(sv.z, sv.w)));
        }
#pragma unroll
        for (int o = 16; o > 0; o >>= 1)
            m = fmaxf(m, __shfl_xor_sync(0xffffffffu, m, o));

        const float* srow = g_s + ((size_t)(b * T + t0 + w)) * T;
        float sum = 0.f;
#pragma unroll 8
        for (int i = 0; i < 64; i++) {
            int vi = i * 32 + lane;
            float e = __expf(srow[vi] - m);
            attH[w * ATP + vi] = __float2half_rn(e);
            sum += e;
        }
#pragma unroll
        for (int o = 16; o > 0; o >>= 1)
            sum += __shfl_xor_sync(0xffffffffu, sum, o);
        if (lane == 0) invl[w] = 1.f / sum;
    }

    const int hf = w & 1;
    const int ht = w >> 1;
    float d[4] = {0.f, 0.f, 0.f, 0.f};

    const int sel   = tid >> 8;
    const int hh    = (tid & 255) >> 2;
    const int cpair = tid & 3;
    const __half* vsrc = (sel ? g_vtlo : g_vthi) + (size_t)(b * HS + hh) * T;

#pragma unroll
    for (int u = 0; u < 2; u++) {
        int c16 = cpair * 2 + u;
        cp_async16(&Vts[((0 * 2 + sel) * 64 + hh) * VTP + c16 * 8], vsrc + c16 * 8);
    }
    cp_commit();

    const int NT = T / 64;
    for (int ck = 0; ck < NT; ck++) {
        const int buf = ck & 1;
        cp_wait<0>();
        __syncthreads();

        if (ck + 1 < NT) {
            const __half* src2 = vsrc + (ck + 1) * 64;
#pragma unroll
            for (int u = 0; u < 2; u++) {
                int c16 = cpair * 2 + u;
                cp_async16(&Vts[(((buf ^ 1) * 2 + sel) * 64 + hh) * VTP + c16 * 8],
                           src2 + c16 * 8);
            }
            cp_commit();
        }

        const int v0 = ck * 64;
#pragma unroll
        for (int ks = 0; ks < 2; ks++) {
            int vloc = hf * 32 + ks * 16;
            const __half* ap = attH + g * ATP + v0 + vloc + 2 * tig;
            unsigned a0 = *(const unsigned*)(ap);
            unsigned a1 = *(const unsigned*)(ap + 8 * ATP);
            unsigned a2 = *(const unsigned*)(ap + 8);
            unsigned a3 = *(const unsigned*)(ap + 8 * ATP + 8);
            const __half* bh = &Vts[((buf * 2 + 0) * 64 + ht * 8 + g) * VTP + vloc + 2 * tig];
            mma_f16(d, a0, a1, a2, a3,
                    *(const unsigned*)bh, *(const unsigned*)(bh + 8));
            const __half* bl = &Vts[((buf * 2 + 1) * 64 + ht * 8 + g) * VTP + vloc + 2 * tig];
            mma_f16(d, a0, a1, a2, a3,
                    *(const unsigned*)bl, *(const unsigned*)(bl + 8));
        }
    }

    {
        float* pw = pout + w * 128;
        *(float2*)&pw[g * 8 + 2 * tig]       = make_float2(d[0], d[1]);
        *(float2*)&pw[(g + 8) * 8 + 2 * tig] = make_float2(d[2], d[3]);
    }
    __syncthreads();

    {
        int t   = tid >> 5;
        int hl  = tid & 31;
        int ht2 = hl >> 2;
        int hloc = (hl & 3) * 2;
        float2 p0 = *(const float2*)&pout[(ht2 * 2 + 0) * 128 + t * 8 + hloc];
        float2 p1 = *(const float2*)&pout[(ht2 * 2 + 1) * 128 + t * 8 + hloc];
        float sc = invl[t];
        *(float2*)(out + ((size_t)(b * T + t0 + t)) * HS + hl * 2) =
            make_float2((p0.x + p1.x) * sc, (p0.y + p1.y) * sc);
    }
}

// =====================================================================
extern "C" void kernel_launch(void* const* d_in, const int* in_sizes, int n_in,
                              void* d_out, int out_size)
{
    (void)in_sizes; (void)n_in; (void)out_size;
    const float* x   = (const float*)d_in[0];
    const float* Wk  = (const float*)d_in[1];
    const float* bk  = (const float*)d_in[2];
    const float* Wq  = (const float*)d_in[3];
    const float* bq  = (const float*)d_in[4];
    const float* Wv  = (const float*)d_in[5];
    const float* bv  = (const float*)d_in[6];
    const float* rel = (const float*)d_in[7];
    float* out = (float*)d_out;

    split_kernel<<<16384 + 192, 256>>>(x, Wk, Wq, Wv);

    const int pj_smem = 2 * PJ_BUF_BYTES;
    cudaFuncSetAttribute(proj_mma_kernel, cudaFuncAttributeMaxDynamicSharedMemorySize, pj_smem);
    proj_mma_kernel<<<128, 256, pj_smem>>>(bk, bq, bv);

    const int qk_smem = 4 * 128 * QKP * (int)sizeof(__nv_bfloat16);
    cudaFuncSetAttribute(qk_mma_kernel, cudaFuncAttributeMaxDynamicSharedMemorySize, qk_smem);
    qk_mma_kernel<<<dim3(T / 128, T / 128, B), 256, qk_smem>>>();

    rel_kernel<<<T, 256>>>(rel);

    const int k3_smem = 65792 + 36864 + 8192;
    cudaFuncSetAttribute(soft_pv_kernel, cudaFuncAttributeMaxDynamicSharedMemorySize, k3_smem);
    soft_pv_kernel<<<dim3(T / 16, B), 512, k3_smem>>>(out);
}